// round 9
// baseline (speedup 1.0000x reference)
#include <cuda_runtime.h>
#include <cstdint>
#include <cstdio>

// Bidirectional GRU encoder: B=64, T=512, E=512, U=1024, gates (z,r,h), reset_after=True.
// out = [B,T,2U] outputs (fwd|bwd) followed by [B,2U] final state.
//
// v9: thread tile 2j x 8b (24 FFMA2 : 5 LDS per k), split-K x4 (256 threads),
// per-thread-owned output slices so reduction + epilogue run on all threads.

#define TT   512   // seq len
#define BB   64    // batch
#define EE   512   // embedding dim
#define UU   1024  // units
#define KC   64    // K-chunk
#define NB   128   // total blocks in persistent kernel (64 per direction)
#define NTHR 256   // threads per block (2 warps per SMSP, 4 split-K groups)

typedef unsigned long long ull;

// ---------------- device scratch (static only — no cudaMalloc allowed) ----------------
__device__ __align__(16) float g_Xt[(size_t)TT * EE * BB];   // [t][e][64], 64 MB
__device__ __align__(16) float g_Ht[2][2][UU * BB];          // [dir][parity][u][64], 1 MB
__device__ __align__(16) ull   g_maskB[TT];                  // bit b = (enc[b][t] != 0)
__device__ unsigned g_count;                                 // global barrier counter

// ---------------- helpers ----------------
__device__ __forceinline__ ull fma2(ull a, ull b, ull c) {
    ull d;
    asm("fma.rn.f32x2 %0, %1, %2, %3;" : "=l"(d) : "l"(a), "l"(b), "l"(c));
    return d;
}
__device__ __forceinline__ ull add2(ull a, ull b) {
    ull d;
    asm("add.rn.f32x2 %0, %1, %2;" : "=l"(d) : "l"(a), "l"(b));
    return d;
}
__device__ __forceinline__ float lo32(ull v) { return __uint_as_float((unsigned)v); }
__device__ __forceinline__ float hi32(ull v) { return __uint_as_float((unsigned)(v >> 32)); }

__device__ __forceinline__ void cp16(void* s, const void* g) {
    unsigned sa = (unsigned)__cvta_generic_to_shared(s);
    // .cg: bypass L1. REQUIRED for g_Ht (cross-SM producer/consumer; L1 not coherent).
    asm volatile("cp.async.cg.shared.global [%0], [%1], 16;" :: "r"(sa), "l"(g));
}
__device__ __forceinline__ void cp_commit() { asm volatile("cp.async.commit_group;" ::: "memory"); }
__device__ __forceinline__ void cp_wait1()  { asm volatile("cp.async.wait_group 1;" ::: "memory"); }
__device__ __forceinline__ void cp_wait0()  { asm volatile("cp.async.wait_group 0;" ::: "memory"); }

// ---------------- prep: Xt[t][e][b] = emb[enc[b][t]][e] ----------------
__global__ void prep_kernel(const int* __restrict__ enc, const float* __restrict__ emb) {
    int t = blockIdx.x;
    __shared__ int tok[BB];
    if (threadIdx.x < BB) tok[threadIdx.x] = enc[threadIdx.x * TT + t];
    __syncthreads();
    for (int i = threadIdx.x; i < BB * (EE / 4); i += blockDim.x) {
        int e4 = i >> 6;
        int b  = i & 63;
        float4 v = *(const float4*)(emb + (size_t)tok[b] * EE + e4 * 4);
        size_t base = ((size_t)t * EE + (size_t)e4 * 4) * BB + b;
        g_Xt[base]          = v.x;
        g_Xt[base + BB]     = v.y;
        g_Xt[base + 2 * BB] = v.z;
        g_Xt[base + 3 * BB] = v.w;
    }
}

// ---------------- mask: pack enc!=0 into one uint64 per t ----------------
__global__ void mask_kernel(const int* __restrict__ enc) {
    int t = blockIdx.x * blockDim.x + threadIdx.x;
    if (t < TT) {
        ull m = 0;
        for (int b = 0; b < BB; b++)
            m |= (ull)(enc[b * TT + t] != 0) << b;
        g_maskB[t] = m;
    }
}

// ---------------- init: h0 -> g_Ht[dir][0]; reset barrier ----------------
__global__ void init_kernel(const float* __restrict__ h0f, const float* __restrict__ h0b) {
    int i = blockIdx.x * blockDim.x + threadIdx.x;  // 0 .. 131071
    if (i == 0) g_count = 0u;
    int d = i >> 16;
    int r = i & 65535;
    int u = r >> 6;
    int b = r & 63;
    const float* h0 = d ? h0b : h0f;
    g_Ht[d][0][u * BB + b] = h0[b * UU + u];
}

// ---------------- GEMM building blocks ----------------
// a-chunk: [KC][64] floats, 16 KB contiguous
__device__ __forceinline__ void load_a(float* dst, const float* src) {
#pragma unroll
    for (int i = 0; i < 4; i++) {
        int idx = i * NTHR + threadIdx.x;  // float4 index, 1024 total
        cp16(dst + idx * 4, src + idx * 4);
    }
    cp_commit();
}

// w-chunk, stored DUPLICATED per j-pair:
// ws byte offset (k, q=jpair, gate) = k*384 + q*48 + gate*16, content {w_j,w_j,w_j1,w_j1}
__device__ __forceinline__ void ldg_w(const float* __restrict__ W, int k0, int j0, float2* v) {
#pragma unroll
    for (int i = 0; i < 6; i++) {
        int idx  = i * NTHR + threadIdx.x;   // 0..1535 float2 slots
        int k    = idx / 24, rem = idx - k * 24;
        int gate = rem >> 3;
        int q    = rem & 7;
        v[i] = *(const float2*)(W + (size_t)(k0 + k) * 3072 + (gate << 10) + j0 + 2 * q);
    }
}
__device__ __forceinline__ void sts_w(float* ws, const float2* v) {
    float4* w4p = (float4*)ws;
#pragma unroll
    for (int i = 0; i < 6; i++) {
        int idx  = i * NTHR + threadIdx.x;
        int k    = idx / 24, rem = idx - k * 24;
        int gate = rem >> 3;
        int q    = rem & 7;
        w4p[k * 24 + q * 3 + gate] = make_float4(v[i].x, v[i].x, v[i].y, v[i].y);
    }
}

// per-chunk compute, split-K x4: group g handles k in [g*16, g*16+16).
// thread = (jp, bg): 2 j-cols x 8 batch rows (bg*8 .. bg*8+7).
// accumulators acc[jj*4 + bu], lanes = batch pair (bg*8+2bu, +1).
__device__ __forceinline__ void compute_chunk(const float* as, const float* ws,
                                              int g, int jp, int bg,
                                              ull* az, ull* ar, ull* ah) {
    const char* wb = (const char*)ws + jp * 48 + (size_t)g * 16 * 384;
    const char* ab = (const char*)as + bg * 32 + (size_t)g * 16 * 256;
#pragma unroll 4
    for (int k = 0; k < 16; k++) {
        ulonglong2 wz = *(const ulonglong2*)(wb + (size_t)k * 384);        // {dup wz_j, dup wz_j1}
        ulonglong2 wr = *(const ulonglong2*)(wb + (size_t)k * 384 + 16);
        ulonglong2 wh = *(const ulonglong2*)(wb + (size_t)k * 384 + 32);
        ulonglong2 aA = *(const ulonglong2*)(ab + (size_t)k * 256);        // bu0, bu1
        ulonglong2 aB = *(const ulonglong2*)(ab + (size_t)k * 256 + 16);   // bu2, bu3
        az[0] = fma2(aA.x, wz.x, az[0]); az[1] = fma2(aA.y, wz.x, az[1]);
        az[2] = fma2(aB.x, wz.x, az[2]); az[3] = fma2(aB.y, wz.x, az[3]);
        az[4] = fma2(aA.x, wz.y, az[4]); az[5] = fma2(aA.y, wz.y, az[5]);
        az[6] = fma2(aB.x, wz.y, az[6]); az[7] = fma2(aB.y, wz.y, az[7]);
        ar[0] = fma2(aA.x, wr.x, ar[0]); ar[1] = fma2(aA.y, wr.x, ar[1]);
        ar[2] = fma2(aB.x, wr.x, ar[2]); ar[3] = fma2(aB.y, wr.x, ar[3]);
        ar[4] = fma2(aA.x, wr.y, ar[4]); ar[5] = fma2(aA.y, wr.y, ar[5]);
        ar[6] = fma2(aB.x, wr.y, ar[6]); ar[7] = fma2(aB.y, wr.y, ar[7]);
        ah[0] = fma2(aA.x, wh.x, ah[0]); ah[1] = fma2(aA.y, wh.x, ah[1]);
        ah[2] = fma2(aB.x, wh.x, ah[2]); ah[3] = fma2(aB.y, wh.x, ah[3]);
        ah[4] = fma2(aA.x, wh.y, ah[4]); ah[5] = fma2(aA.y, wh.y, ah[5]);
        ah[6] = fma2(aB.x, wh.y, ah[6]); ah[7] = fma2(aB.y, wh.y, ah[7]);
    }
}

// double-buffered chunked GEMM accumulation over nch chunks of KC
__device__ __forceinline__ void gemm_phase(const float* abase, const float* __restrict__ W,
                                           int j0, int nch,
                                           float* as0, float* as1, float* ws0, float* ws1,
                                           int g, int jp, int bg,
                                           ull* az, ull* ar, ull* ah) {
    float2 v[6];
    ldg_w(W, 0, j0, v);
    sts_w(ws0, v);
    load_a(as0, abase);
    for (int c = 0; c < nch; c++) {
        float* ac = (c & 1) ? as1 : as0;
        float* wc = (c & 1) ? ws1 : ws0;
        if (c + 1 < nch) {
            float* an = (c & 1) ? as0 : as1;
            load_a(an, abase + (size_t)(c + 1) * KC * BB);
            ldg_w(W, (c + 1) * KC, j0, v);
            cp_wait1();
        } else {
            cp_wait0();
        }
        __syncthreads();
        compute_chunk(ac, wc, g, jp, bg, az, ar, ah);
        if (c + 1 < nch) {
            float* wn = (c & 1) ? ws0 : ws1;
            sts_w(wn, v);
        }
        __syncthreads();
    }
}

// ---------------- persistent recurrent kernel ----------------
__global__ void __launch_bounds__(NTHR, 1)
gru_kernel(const float* __restrict__ Wx_f, const float* __restrict__ Wh_f, const float* __restrict__ b_f,
           const float* __restrict__ Wx_b, const float* __restrict__ Wh_b, const float* __restrict__ b_b,
           float* __restrict__ out) {
    extern __shared__ char smem_raw[];
    float* as0 = (float*)smem_raw;                 // [KC][64]       16 KB
    float* as1 = as0 + KC * BB;                    //                16 KB
    float* ws0 = as1 + KC * BB;                    // [KC][8][48B]   24 KB (reduce scratch lo)
    float* ws1 = ws0 + KC * 96;                    //                24 KB (reduce scratch hi)
    ull*  maskS = (ull*)(ws1 + KC * 96);           // [TT]            4 KB

    const int bid = blockIdx.x, tid = threadIdx.x;
    const int d   = bid >> 6;                 // direction
    const int p   = bid & 63;                 // block within direction
    const int j0  = p << 4;                   // 16 j-columns per block
    const int g   = tid >> 6;                 // split-K group 0..3
    const int r   = tid & 63;
    const int jp  = r >> 3;                   // 0..7 -> j = j0+2jp, +1
    const int bg  = r & 7;                    // 0..7 -> b tile [bg*8, bg*8+8)
    const int j   = j0 + 2 * jp;
    const int bO  = bg * 8 + 2 * g;           // owned batch pair (bO, bO+1), slice bu = g

    // stage mask bitmap (4 KB = 256 threads x 16B)
    cp16(maskS + tid * 2, g_maskB + tid * 2);
    cp_commit();

    const float* Wx   = d ? Wx_b : Wx_f;
    const float* Wh   = d ? Wh_b : Wh_f;
    const float* bias = d ? b_b  : b_f;
    float bz[2], br[2], bx[2], bh[2];
#pragma unroll
    for (int jj = 0; jj < 2; jj++) {
        bz[jj] = bias[j + jj]        + bias[3072 + j + jj];
        br[jj] = bias[1024 + j + jj] + bias[4096 + j + jj];
        bx[jj] = bias[2048 + j + jj];
        bh[jj] = bias[5120 + j + jj];
    }

    // owned state: hreg[jj][l], oreg[jj][l], l in {0,1} -> b = bO + l
    float hreg[2][2], oreg[2][2];
#pragma unroll
    for (int jj = 0; jj < 2; jj++)
#pragma unroll
        for (int l = 0; l < 2; l++) {
            hreg[jj][l] = g_Ht[d][0][(j + jj) * BB + bO + l];
            oreg[jj][l] = 0.f;
        }

    // accumulators acc[jj*4 + bu]
    ull az[8], ar[8], axh[8], ahh[8];
#pragma unroll
    for (int i = 0; i < 8; i++) { az[i] = 0; ar[i] = 0; axh[i] = 0; ahh[i] = 0; }

    // x-part of step 0
    {
        int t0 = d ? (TT - 1) : 0;
        gemm_phase(g_Xt + (size_t)t0 * EE * BB, Wx, j0, EE / KC,
                   as0, as1, ws0, ws1, g, jp, bg, az, ar, axh);
    }

    for (int s = 0;; s++) {
        const int t   = d ? (TT - 1 - s) : s;
        const int par = s & 1;

        // recurrent part: hg += h @ Wh
        gemm_phase(g_Ht[d][par], Wh, j0, UU / KC,
                   as0, as1, ws0, ws1, g, jp, bg, az, ar, ahh);

        // ---- cross-group reduce via scratch overlaid on ws0..ws1 (48 KB, dead now) ----
        // slot((owner bu)*64 + jp*8 + bg, contributor c) of 8 ull each
        ull* red = (ull*)ws0;
#pragma unroll
        for (int bu = 0; bu < 4; bu++) {
            if (bu == g) continue;
            int c = g - (g > bu ? 1 : 0);
            ull* dst = red + (size_t)(((bu << 6) + r) * 3 + c) * 8;
            dst[0] = az[bu];      dst[1] = az[4 + bu];
            dst[2] = ar[bu];      dst[3] = ar[4 + bu];
            dst[4] = axh[bu];     dst[5] = axh[4 + bu];
            dst[6] = ahh[bu];     dst[7] = ahh[4 + bu];
        }
        __syncthreads();

        ull sz0 = az[g],  sz1 = az[4 + g];
        ull sr0 = ar[g],  sr1 = ar[4 + g];
        ull sx0 = axh[g], sx1 = axh[4 + g];
        ull sh0 = ahh[g], sh1 = ahh[4 + g];
        {
            const ull* src = red + (size_t)(((g << 6) + r) * 3) * 8;
#pragma unroll
            for (int c = 0; c < 3; c++) {
                const ull* sp = src + c * 8;
                sz0 = add2(sz0, sp[0]); sz1 = add2(sz1, sp[1]);
                sr0 = add2(sr0, sp[2]); sr1 = add2(sr1, sp[3]);
                sx0 = add2(sx0, sp[4]); sx1 = add2(sx1, sp[5]);
                sh0 = add2(sh0, sp[6]); sh1 = add2(sh1, sp[7]);
            }
        }

        // ---- epilogue: gates, masking, writes (all threads, 4 outputs each) ----
        {
            const ull mv = maskS[t];
            const size_t ocol = (size_t)t * 2048 + (size_t)d * UU + j;
            float hv[2][2];
            ull zacc[2] = { sz0, sz1 }, racc[2] = { sr0, sr1 };
            ull xacc[2] = { sx0, sx1 }, hacc[2] = { sh0, sh1 };
#pragma unroll
            for (int l = 0; l < 2; l++) {
                const bool m = (mv >> (bO + l)) & 1ull;
#pragma unroll
                for (int jj = 0; jj < 2; jj++) {
                    float zs = l ? hi32(zacc[jj]) : lo32(zacc[jj]);
                    float rs = l ? hi32(racc[jj]) : lo32(racc[jj]);
                    float xs = l ? hi32(xacc[jj]) : lo32(xacc[jj]);
                    float hs = l ? hi32(hacc[jj]) : lo32(hacc[jj]);
                    float ez = __expf(-(zs + bz[jj]));
                    float z  = __fdividef(1.f, 1.f + ez);
                    float er = __expf(-(rs + br[jj]));
                    float rg = __fdividef(1.f, 1.f + er);
                    float hc = tanhf(xs + bx[jj] + rg * (hs + bh[jj]));
                    float hn = z * hreg[jj][l] + (1.f - z) * hc;
                    hn = m ? hn : hreg[jj][l];
                    float o = m ? hn : oreg[jj][l];
                    hreg[jj][l] = hn;
                    oreg[jj][l] = o;
                    hv[jj][l] = hn;
                }
            }
            // publish h: STG.64 per j-row (owned batch pair contiguous)
            float* hdst = g_Ht[d][par ^ 1];
#pragma unroll
            for (int jj = 0; jj < 2; jj++)
                *(float2*)&hdst[(j + jj) * BB + bO] = make_float2(hv[jj][0], hv[jj][1]);
            // outputs: STG.64 per batch row (j, j+1 consecutive)
#pragma unroll
            for (int l = 0; l < 2; l++)
                *(float2*)&out[(size_t)(bO + l) * (TT * 2048) + ocol] =
                    make_float2(oreg[0][l], oreg[1][l]);
        }

        if (s == TT - 1) break;

        // arrive: h(s+1) published (sync also protects scratch before ws reuse)
        __syncthreads();
        if (tid == 0) { __threadfence(); atomicAdd(&g_count, 1u); }

        // zero accs; hide barrier latency with x-part of step s+1 (independent of h)
#pragma unroll
        for (int i = 0; i < 8; i++) { az[i] = 0; ar[i] = 0; axh[i] = 0; ahh[i] = 0; }
        {
            int tn = d ? (TT - 2 - s) : (s + 1);
            gemm_phase(g_Xt + (size_t)tn * EE * BB, Wx, j0, EE / KC,
                       as0, as1, ws0, ws1, g, jp, bg, az, ar, axh);
        }

        // wait: everyone published h(s+1)
        if (tid == 0) {
            unsigned tgt = (unsigned)(s + 1) * NB;
            volatile unsigned* pc = &g_count;
            while (*pc < tgt) { __nanosleep(32); }
            __threadfence();
        }
        __syncthreads();
    }

    // final state: [B, 2U] after the output block
    {
        const size_t STATE_OFF = (size_t)BB * TT * 2048;
#pragma unroll
        for (int l = 0; l < 2; l++)
            *(float2*)&out[STATE_OFF + (size_t)(bO + l) * 2048 + (size_t)d * UU + j] =
                make_float2(hreg[0][l], hreg[1][l]);
    }
}

// ---------------- launcher ----------------
extern "C" void kernel_launch(void* const* d_in, const int* in_sizes, int n_in,
                              void* d_out, int out_size) {
    (void)in_sizes; (void)n_in; (void)out_size;
    const int*   enc = (const int*)  d_in[0];
    const float* h0f = (const float*)d_in[1];
    const float* h0b = (const float*)d_in[2];
    const float* emb = (const float*)d_in[3];
    const float* Wxf = (const float*)d_in[4];
    const float* Whf = (const float*)d_in[5];
    const float* bf  = (const float*)d_in[6];
    const float* Wxb = (const float*)d_in[7];
    const float* Whb = (const float*)d_in[8];
    const float* bb  = (const float*)d_in[9];
    float* out = (float*)d_out;

    // 116 KB dynamic smem: ~84 KB used, padded so at most ONE block fits per SM
    // -> all 128 persistent blocks land on distinct SMs (barrier-safe, no SM sharing).
    const int SMEM_BYTES = 116 * 1024;
    cudaFuncSetAttribute(gru_kernel, cudaFuncAttributeMaxDynamicSharedMemorySize, SMEM_BYTES);

    prep_kernel<<<TT, 256>>>(enc, emb);
    mask_kernel<<<2, 256>>>(enc);
    init_kernel<<<512, 256>>>(h0f, h0b);
    gru_kernel<<<NB, NTHR, SMEM_BYTES>>>(Wxf, Whf, bf, Wxb, Whb, bb, out);
}

// round 10
// speedup vs baseline: 1.0007x; 1.0007x over previous
#include <cuda_runtime.h>
#include <cstdint>
#include <cstdio>

// Bidirectional GRU encoder: B=64, T=512, E=512, U=1024, gates (z,r,h), reset_after=True.
// out = [B,T,2U] outputs (fwd|bwd) followed by [B,2U] final state.
//
// v9: thread tile 2j x 8b (24 FFMA2 : 5 LDS per k), split-K x4 (256 threads),
// per-thread-owned output slices so reduction + epilogue run on all threads.

#define TT   512   // seq len
#define BB   64    // batch
#define EE   512   // embedding dim
#define UU   1024  // units
#define KC   64    // K-chunk
#define NB   128   // total blocks in persistent kernel (64 per direction)
#define NTHR 256   // threads per block (2 warps per SMSP, 4 split-K groups)

typedef unsigned long long ull;

// ---------------- device scratch (static only — no cudaMalloc allowed) ----------------
__device__ __align__(16) float g_Xt[(size_t)TT * EE * BB];   // [t][e][64], 64 MB
__device__ __align__(16) float g_Ht[2][2][UU * BB];          // [dir][parity][u][64], 1 MB
__device__ __align__(16) ull   g_maskB[TT];                  // bit b = (enc[b][t] != 0)
__device__ unsigned g_count;                                 // global barrier counter

// ---------------- helpers ----------------
__device__ __forceinline__ ull fma2(ull a, ull b, ull c) {
    ull d;
    asm("fma.rn.f32x2 %0, %1, %2, %3;" : "=l"(d) : "l"(a), "l"(b), "l"(c));
    return d;
}
__device__ __forceinline__ ull add2(ull a, ull b) {
    ull d;
    asm("add.rn.f32x2 %0, %1, %2;" : "=l"(d) : "l"(a), "l"(b));
    return d;
}
__device__ __forceinline__ float lo32(ull v) { return __uint_as_float((unsigned)v); }
__device__ __forceinline__ float hi32(ull v) { return __uint_as_float((unsigned)(v >> 32)); }

__device__ __forceinline__ void cp16(void* s, const void* g) {
    unsigned sa = (unsigned)__cvta_generic_to_shared(s);
    // .cg: bypass L1. REQUIRED for g_Ht (cross-SM producer/consumer; L1 not coherent).
    asm volatile("cp.async.cg.shared.global [%0], [%1], 16;" :: "r"(sa), "l"(g));
}
__device__ __forceinline__ void cp_commit() { asm volatile("cp.async.commit_group;" ::: "memory"); }
__device__ __forceinline__ void cp_wait1()  { asm volatile("cp.async.wait_group 1;" ::: "memory"); }
__device__ __forceinline__ void cp_wait0()  { asm volatile("cp.async.wait_group 0;" ::: "memory"); }

// ---------------- prep: Xt[t][e][b] = emb[enc[b][t]][e] ----------------
__global__ void prep_kernel(const int* __restrict__ enc, const float* __restrict__ emb) {
    int t = blockIdx.x;
    __shared__ int tok[BB];
    if (threadIdx.x < BB) tok[threadIdx.x] = enc[threadIdx.x * TT + t];
    __syncthreads();
    for (int i = threadIdx.x; i < BB * (EE / 4); i += blockDim.x) {
        int e4 = i >> 6;
        int b  = i & 63;
        float4 v = *(const float4*)(emb + (size_t)tok[b] * EE + e4 * 4);
        size_t base = ((size_t)t * EE + (size_t)e4 * 4) * BB + b;
        g_Xt[base]          = v.x;
        g_Xt[base + BB]     = v.y;
        g_Xt[base + 2 * BB] = v.z;
        g_Xt[base + 3 * BB] = v.w;
    }
}

// ---------------- mask: pack enc!=0 into one uint64 per t ----------------
__global__ void mask_kernel(const int* __restrict__ enc) {
    int t = blockIdx.x * blockDim.x + threadIdx.x;
    if (t < TT) {
        ull m = 0;
        for (int b = 0; b < BB; b++)
            m |= (ull)(enc[b * TT + t] != 0) << b;
        g_maskB[t] = m;
    }
}

// ---------------- init: h0 -> g_Ht[dir][0]; reset barrier ----------------
__global__ void init_kernel(const float* __restrict__ h0f, const float* __restrict__ h0b) {
    int i = blockIdx.x * blockDim.x + threadIdx.x;  // 0 .. 131071
    if (i == 0) g_count = 0u;
    int d = i >> 16;
    int r = i & 65535;
    int u = r >> 6;
    int b = r & 63;
    const float* h0 = d ? h0b : h0f;
    g_Ht[d][0][u * BB + b] = h0[b * UU + u];
}

// ---------------- GEMM building blocks ----------------
// a-chunk: [KC][64] floats, 16 KB contiguous
__device__ __forceinline__ void load_a(float* dst, const float* src) {
#pragma unroll
    for (int i = 0; i < 4; i++) {
        int idx = i * NTHR + threadIdx.x;  // float4 index, 1024 total
        cp16(dst + idx * 4, src + idx * 4);
    }
    cp_commit();
}

// w-chunk, stored DUPLICATED per j-pair:
// ws byte offset (k, q=jpair, gate) = k*384 + q*48 + gate*16, content {w_j,w_j,w_j1,w_j1}
__device__ __forceinline__ void ldg_w(const float* __restrict__ W, int k0, int j0, float2* v) {
#pragma unroll
    for (int i = 0; i < 6; i++) {
        int idx  = i * NTHR + threadIdx.x;   // 0..1535 float2 slots
        int k    = idx / 24, rem = idx - k * 24;
        int gate = rem >> 3;
        int q    = rem & 7;
        v[i] = *(const float2*)(W + (size_t)(k0 + k) * 3072 + (gate << 10) + j0 + 2 * q);
    }
}
__device__ __forceinline__ void sts_w(float* ws, const float2* v) {
    float4* w4p = (float4*)ws;
#pragma unroll
    for (int i = 0; i < 6; i++) {
        int idx  = i * NTHR + threadIdx.x;
        int k    = idx / 24, rem = idx - k * 24;
        int gate = rem >> 3;
        int q    = rem & 7;
        w4p[k * 24 + q * 3 + gate] = make_float4(v[i].x, v[i].x, v[i].y, v[i].y);
    }
}

// per-chunk compute, split-K x4: group g handles k in [g*16, g*16+16).
// thread = (jp, bg): 2 j-cols x 8 batch rows (bg*8 .. bg*8+7).
// accumulators acc[jj*4 + bu], lanes = batch pair (bg*8+2bu, +1).
__device__ __forceinline__ void compute_chunk(const float* as, const float* ws,
                                              int g, int jp, int bg,
                                              ull* az, ull* ar, ull* ah) {
    const char* wb = (const char*)ws + jp * 48 + (size_t)g * 16 * 384;
    const char* ab = (const char*)as + bg * 32 + (size_t)g * 16 * 256;
#pragma unroll 4
    for (int k = 0; k < 16; k++) {
        ulonglong2 wz = *(const ulonglong2*)(wb + (size_t)k * 384);        // {dup wz_j, dup wz_j1}
        ulonglong2 wr = *(const ulonglong2*)(wb + (size_t)k * 384 + 16);
        ulonglong2 wh = *(const ulonglong2*)(wb + (size_t)k * 384 + 32);
        ulonglong2 aA = *(const ulonglong2*)(ab + (size_t)k * 256);        // bu0, bu1
        ulonglong2 aB = *(const ulonglong2*)(ab + (size_t)k * 256 + 16);   // bu2, bu3
        az[0] = fma2(aA.x, wz.x, az[0]); az[1] = fma2(aA.y, wz.x, az[1]);
        az[2] = fma2(aB.x, wz.x, az[2]); az[3] = fma2(aB.y, wz.x, az[3]);
        az[4] = fma2(aA.x, wz.y, az[4]); az[5] = fma2(aA.y, wz.y, az[5]);
        az[6] = fma2(aB.x, wz.y, az[6]); az[7] = fma2(aB.y, wz.y, az[7]);
        ar[0] = fma2(aA.x, wr.x, ar[0]); ar[1] = fma2(aA.y, wr.x, ar[1]);
        ar[2] = fma2(aB.x, wr.x, ar[2]); ar[3] = fma2(aB.y, wr.x, ar[3]);
        ar[4] = fma2(aA.x, wr.y, ar[4]); ar[5] = fma2(aA.y, wr.y, ar[5]);
        ar[6] = fma2(aB.x, wr.y, ar[6]); ar[7] = fma2(aB.y, wr.y, ar[7]);
        ah[0] = fma2(aA.x, wh.x, ah[0]); ah[1] = fma2(aA.y, wh.x, ah[1]);
        ah[2] = fma2(aB.x, wh.x, ah[2]); ah[3] = fma2(aB.y, wh.x, ah[3]);
        ah[4] = fma2(aA.x, wh.y, ah[4]); ah[5] = fma2(aA.y, wh.y, ah[5]);
        ah[6] = fma2(aB.x, wh.y, ah[6]); ah[7] = fma2(aB.y, wh.y, ah[7]);
    }
}

// double-buffered chunked GEMM accumulation over nch chunks of KC
__device__ __forceinline__ void gemm_phase(const float* abase, const float* __restrict__ W,
                                           int j0, int nch,
                                           float* as0, float* as1, float* ws0, float* ws1,
                                           int g, int jp, int bg,
                                           ull* az, ull* ar, ull* ah) {
    float2 v[6];
    ldg_w(W, 0, j0, v);
    sts_w(ws0, v);
    load_a(as0, abase);
    for (int c = 0; c < nch; c++) {
        float* ac = (c & 1) ? as1 : as0;
        float* wc = (c & 1) ? ws1 : ws0;
        if (c + 1 < nch) {
            float* an = (c & 1) ? as0 : as1;
            load_a(an, abase + (size_t)(c + 1) * KC * BB);
            ldg_w(W, (c + 1) * KC, j0, v);
            cp_wait1();
        } else {
            cp_wait0();
        }
        __syncthreads();
        compute_chunk(ac, wc, g, jp, bg, az, ar, ah);
        if (c + 1 < nch) {
            float* wn = (c & 1) ? ws0 : ws1;
            sts_w(wn, v);
        }
        __syncthreads();
    }
}

// ---------------- persistent recurrent kernel ----------------
__global__ void __launch_bounds__(NTHR, 1)
gru_kernel(const float* __restrict__ Wx_f, const float* __restrict__ Wh_f, const float* __restrict__ b_f,
           const float* __restrict__ Wx_b, const float* __restrict__ Wh_b, const float* __restrict__ b_b,
           float* __restrict__ out) {
    extern __shared__ char smem_raw[];
    float* as0 = (float*)smem_raw;                 // [KC][64]       16 KB
    float* as1 = as0 + KC * BB;                    //                16 KB
    float* ws0 = as1 + KC * BB;                    // [KC][8][48B]   24 KB (reduce scratch lo)
    float* ws1 = ws0 + KC * 96;                    //                24 KB (reduce scratch hi)
    ull*  maskS = (ull*)(ws1 + KC * 96);           // [TT]            4 KB

    const int bid = blockIdx.x, tid = threadIdx.x;
    const int d   = bid >> 6;                 // direction
    const int p   = bid & 63;                 // block within direction
    const int j0  = p << 4;                   // 16 j-columns per block
    const int g   = tid >> 6;                 // split-K group 0..3
    const int r   = tid & 63;
    const int jp  = r >> 3;                   // 0..7 -> j = j0+2jp, +1
    const int bg  = r & 7;                    // 0..7 -> b tile [bg*8, bg*8+8)
    const int j   = j0 + 2 * jp;
    const int bO  = bg * 8 + 2 * g;           // owned batch pair (bO, bO+1), slice bu = g

    // stage mask bitmap (4 KB = 256 threads x 16B)
    cp16(maskS + tid * 2, g_maskB + tid * 2);
    cp_commit();

    const float* Wx   = d ? Wx_b : Wx_f;
    const float* Wh   = d ? Wh_b : Wh_f;
    const float* bias = d ? b_b  : b_f;
    float bz[2], br[2], bx[2], bh[2];
#pragma unroll
    for (int jj = 0; jj < 2; jj++) {
        bz[jj] = bias[j + jj]        + bias[3072 + j + jj];
        br[jj] = bias[1024 + j + jj] + bias[4096 + j + jj];
        bx[jj] = bias[2048 + j + jj];
        bh[jj] = bias[5120 + j + jj];
    }

    // owned state: hreg[jj][l], oreg[jj][l], l in {0,1} -> b = bO + l
    float hreg[2][2], oreg[2][2];
#pragma unroll
    for (int jj = 0; jj < 2; jj++)
#pragma unroll
        for (int l = 0; l < 2; l++) {
            hreg[jj][l] = g_Ht[d][0][(j + jj) * BB + bO + l];
            oreg[jj][l] = 0.f;
        }

    // accumulators acc[jj*4 + bu]
    ull az[8], ar[8], axh[8], ahh[8];
#pragma unroll
    for (int i = 0; i < 8; i++) { az[i] = 0; ar[i] = 0; axh[i] = 0; ahh[i] = 0; }

    // x-part of step 0
    {
        int t0 = d ? (TT - 1) : 0;
        gemm_phase(g_Xt + (size_t)t0 * EE * BB, Wx, j0, EE / KC,
                   as0, as1, ws0, ws1, g, jp, bg, az, ar, axh);
    }

    for (int s = 0;; s++) {
        const int t   = d ? (TT - 1 - s) : s;
        const int par = s & 1;

        // recurrent part: hg += h @ Wh
        gemm_phase(g_Ht[d][par], Wh, j0, UU / KC,
                   as0, as1, ws0, ws1, g, jp, bg, az, ar, ahh);

        // ---- cross-group reduce via scratch overlaid on ws0..ws1 (48 KB, dead now) ----
        // slot((owner bu)*64 + jp*8 + bg, contributor c) of 8 ull each
        ull* red = (ull*)ws0;
#pragma unroll
        for (int bu = 0; bu < 4; bu++) {
            if (bu == g) continue;
            int c = g - (g > bu ? 1 : 0);
            ull* dst = red + (size_t)(((bu << 6) + r) * 3 + c) * 8;
            dst[0] = az[bu];      dst[1] = az[4 + bu];
            dst[2] = ar[bu];      dst[3] = ar[4 + bu];
            dst[4] = axh[bu];     dst[5] = axh[4 + bu];
            dst[6] = ahh[bu];     dst[7] = ahh[4 + bu];
        }
        __syncthreads();

        ull sz0 = az[g],  sz1 = az[4 + g];
        ull sr0 = ar[g],  sr1 = ar[4 + g];
        ull sx0 = axh[g], sx1 = axh[4 + g];
        ull sh0 = ahh[g], sh1 = ahh[4 + g];
        {
            const ull* src = red + (size_t)(((g << 6) + r) * 3) * 8;
#pragma unroll
            for (int c = 0; c < 3; c++) {
                const ull* sp = src + c * 8;
                sz0 = add2(sz0, sp[0]); sz1 = add2(sz1, sp[1]);
                sr0 = add2(sr0, sp[2]); sr1 = add2(sr1, sp[3]);
                sx0 = add2(sx0, sp[4]); sx1 = add2(sx1, sp[5]);
                sh0 = add2(sh0, sp[6]); sh1 = add2(sh1, sp[7]);
            }
        }

        // ---- epilogue: gates, masking, writes (all threads, 4 outputs each) ----
        {
            const ull mv = maskS[t];
            const size_t ocol = (size_t)t * 2048 + (size_t)d * UU + j;
            float hv[2][2];
            ull zacc[2] = { sz0, sz1 }, racc[2] = { sr0, sr1 };
            ull xacc[2] = { sx0, sx1 }, hacc[2] = { sh0, sh1 };
#pragma unroll
            for (int l = 0; l < 2; l++) {
                const bool m = (mv >> (bO + l)) & 1ull;
#pragma unroll
                for (int jj = 0; jj < 2; jj++) {
                    float zs = l ? hi32(zacc[jj]) : lo32(zacc[jj]);
                    float rs = l ? hi32(racc[jj]) : lo32(racc[jj]);
                    float xs = l ? hi32(xacc[jj]) : lo32(xacc[jj]);
                    float hs = l ? hi32(hacc[jj]) : lo32(hacc[jj]);
                    float ez = __expf(-(zs + bz[jj]));
                    float z  = __fdividef(1.f, 1.f + ez);
                    float er = __expf(-(rs + br[jj]));
                    float rg = __fdividef(1.f, 1.f + er);
                    float hc = tanhf(xs + bx[jj] + rg * (hs + bh[jj]));
                    float hn = z * hreg[jj][l] + (1.f - z) * hc;
                    hn = m ? hn : hreg[jj][l];
                    float o = m ? hn : oreg[jj][l];
                    hreg[jj][l] = hn;
                    oreg[jj][l] = o;
                    hv[jj][l] = hn;
                }
            }
            // publish h: STG.64 per j-row (owned batch pair contiguous)
            float* hdst = g_Ht[d][par ^ 1];
#pragma unroll
            for (int jj = 0; jj < 2; jj++)
                *(float2*)&hdst[(j + jj) * BB + bO] = make_float2(hv[jj][0], hv[jj][1]);
            // outputs: STG.64 per batch row (j, j+1 consecutive)
#pragma unroll
            for (int l = 0; l < 2; l++)
                *(float2*)&out[(size_t)(bO + l) * (TT * 2048) + ocol] =
                    make_float2(oreg[0][l], oreg[1][l]);
        }

        if (s == TT - 1) break;

        // arrive: h(s+1) published (sync also protects scratch before ws reuse)
        __syncthreads();
        if (tid == 0) { __threadfence(); atomicAdd(&g_count, 1u); }

        // zero accs; hide barrier latency with x-part of step s+1 (independent of h)
#pragma unroll
        for (int i = 0; i < 8; i++) { az[i] = 0; ar[i] = 0; axh[i] = 0; ahh[i] = 0; }
        {
            int tn = d ? (TT - 2 - s) : (s + 1);
            gemm_phase(g_Xt + (size_t)tn * EE * BB, Wx, j0, EE / KC,
                       as0, as1, ws0, ws1, g, jp, bg, az, ar, axh);
        }

        // wait: everyone published h(s+1)
        if (tid == 0) {
            unsigned tgt = (unsigned)(s + 1) * NB;
            volatile unsigned* pc = &g_count;
            while (*pc < tgt) { __nanosleep(32); }
            __threadfence();
        }
        __syncthreads();
    }

    // final state: [B, 2U] after the output block
    {
        const size_t STATE_OFF = (size_t)BB * TT * 2048;
#pragma unroll
        for (int l = 0; l < 2; l++)
            *(float2*)&out[STATE_OFF + (size_t)(bO + l) * 2048 + (size_t)d * UU + j] =
                make_float2(hreg[0][l], hreg[1][l]);
    }
}

// ---------------- launcher ----------------
extern "C" void kernel_launch(void* const* d_in, const int* in_sizes, int n_in,
                              void* d_out, int out_size) {
    (void)in_sizes; (void)n_in; (void)out_size;
    const int*   enc = (const int*)  d_in[0];
    const float* h0f = (const float*)d_in[1];
    const float* h0b = (const float*)d_in[2];
    const float* emb = (const float*)d_in[3];
    const float* Wxf = (const float*)d_in[4];
    const float* Whf = (const float*)d_in[5];
    const float* bf  = (const float*)d_in[6];
    const float* Wxb = (const float*)d_in[7];
    const float* Whb = (const float*)d_in[8];
    const float* bb  = (const float*)d_in[9];
    float* out = (float*)d_out;

    // 116 KB dynamic smem: ~84 KB used, padded so at most ONE block fits per SM
    // -> all 128 persistent blocks land on distinct SMs (barrier-safe, no SM sharing).
    const int SMEM_BYTES = 116 * 1024;
    cudaFuncSetAttribute(gru_kernel, cudaFuncAttributeMaxDynamicSharedMemorySize, SMEM_BYTES);

    prep_kernel<<<TT, 256>>>(enc, emb);
    mask_kernel<<<2, 256>>>(enc);
    init_kernel<<<512, 256>>>(h0f, h0b);
    gru_kernel<<<NB, NTHR, SMEM_BYTES>>>(Wxf, Whf, bf, Wxb, Whb, bb, out);
}

// round 12
// speedup vs baseline: 1.1738x; 1.1730x over previous
#include <cuda_runtime.h>
#include <cstdint>
#include <cstdio>

// Bidirectional GRU encoder: B=64, T=512, E=512, U=1024, gates (z,r,h), reset_after=True.
// out = [B,T,2U] outputs (fwd|bwd) followed by [B,2U] final state.
//
// v11 (resubmit after broker failure): 512 threads (4 warps/SMSP) + split-K x4,
// KC=128 (12 chunks/step), R8's per-thread tile (2j x 4b) and single-wavefront warp
// shaping. Reduction + epilogue distributed: each thread owns the (jj,bu) quadrant
// equal to its split-K group.

#define TT   512   // seq len
#define BB   64    // batch
#define EE   512   // embedding dim
#define UU   1024  // units
#define KC   128   // K-chunk
#define NB   128   // total blocks in persistent kernel (64 per direction)
#define NTHR 512   // threads per block (4 warps per SMSP, 4 split-K groups)

typedef unsigned long long ull;

// ---------------- device scratch (static only — no cudaMalloc allowed) ----------------
__device__ __align__(16) float g_Xt[(size_t)TT * EE * BB];   // [t][e][64], 64 MB
__device__ __align__(16) float g_Ht[2][2][UU * BB];          // [dir][parity][u][64], 1 MB
__device__ __align__(16) ull   g_maskB[TT];                  // bit b = (enc[b][t] != 0)
__device__ unsigned g_count;                                 // global barrier counter

// ---------------- helpers ----------------
__device__ __forceinline__ ull fma2(ull a, ull b, ull c) {
    ull d;
    asm("fma.rn.f32x2 %0, %1, %2, %3;" : "=l"(d) : "l"(a), "l"(b), "l"(c));
    return d;
}
__device__ __forceinline__ ull add2(ull a, ull b) {
    ull d;
    asm("add.rn.f32x2 %0, %1, %2;" : "=l"(d) : "l"(a), "l"(b));
    return d;
}
__device__ __forceinline__ float lo32(ull v) { return __uint_as_float((unsigned)v); }
__device__ __forceinline__ float hi32(ull v) { return __uint_as_float((unsigned)(v >> 32)); }

__device__ __forceinline__ void cp16(void* s, const void* g) {
    unsigned sa = (unsigned)__cvta_generic_to_shared(s);
    // .cg: bypass L1. REQUIRED for g_Ht (cross-SM producer/consumer; L1 not coherent).
    asm volatile("cp.async.cg.shared.global [%0], [%1], 16;" :: "r"(sa), "l"(g));
}
__device__ __forceinline__ void cp_commit() { asm volatile("cp.async.commit_group;" ::: "memory"); }
__device__ __forceinline__ void cp_wait1()  { asm volatile("cp.async.wait_group 1;" ::: "memory"); }
__device__ __forceinline__ void cp_wait0()  { asm volatile("cp.async.wait_group 0;" ::: "memory"); }

// ---------------- prep: Xt[t][e][b] = emb[enc[b][t]][e] ----------------
__global__ void prep_kernel(const int* __restrict__ enc, const float* __restrict__ emb) {
    int t = blockIdx.x;
    __shared__ int tok[BB];
    if (threadIdx.x < BB) tok[threadIdx.x] = enc[threadIdx.x * TT + t];
    __syncthreads();
    for (int i = threadIdx.x; i < BB * (EE / 4); i += blockDim.x) {
        int e4 = i >> 6;
        int b  = i & 63;
        float4 v = *(const float4*)(emb + (size_t)tok[b] * EE + e4 * 4);
        size_t base = ((size_t)t * EE + (size_t)e4 * 4) * BB + b;
        g_Xt[base]          = v.x;
        g_Xt[base + BB]     = v.y;
        g_Xt[base + 2 * BB] = v.z;
        g_Xt[base + 3 * BB] = v.w;
    }
}

// ---------------- mask: pack enc!=0 into one uint64 per t ----------------
__global__ void mask_kernel(const int* __restrict__ enc) {
    int t = blockIdx.x * blockDim.x + threadIdx.x;
    if (t < TT) {
        ull m = 0;
        for (int b = 0; b < BB; b++)
            m |= (ull)(enc[b * TT + t] != 0) << b;
        g_maskB[t] = m;
    }
}

// ---------------- init: h0 -> g_Ht[dir][0]; reset barrier ----------------
__global__ void init_kernel(const float* __restrict__ h0f, const float* __restrict__ h0b) {
    int i = blockIdx.x * blockDim.x + threadIdx.x;  // 0 .. 131071
    if (i == 0) g_count = 0u;
    int d = i >> 16;
    int r = i & 65535;
    int u = r >> 6;
    int b = r & 63;
    const float* h0 = d ? h0b : h0f;
    g_Ht[d][0][u * BB + b] = h0[b * UU + u];
}

// ---------------- GEMM building blocks ----------------
// a-chunk: [KC][64] floats, 32 KB contiguous
__device__ __forceinline__ void load_a(float* dst, const float* src) {
#pragma unroll
    for (int i = 0; i < 4; i++) {
        int idx = i * NTHR + threadIdx.x;  // float4 index, 2048 total
        cp16(dst + idx * 4, src + idx * 4);
    }
    cp_commit();
}

// w-chunk, stored DUPLICATED per j-pair:
// ws byte offset (k, q=jpair, gate) = k*384 + q*48 + gate*16, content {w_j,w_j,w_j1,w_j1}
__device__ __forceinline__ void ldg_w(const float* __restrict__ W, int k0, int j0, float2* v) {
#pragma unroll
    for (int i = 0; i < 6; i++) {
        int idx  = i * NTHR + threadIdx.x;   // 0..3071 float2 slots
        int k    = idx / 24, rem = idx - k * 24;
        int gate = rem >> 3;
        int q    = rem & 7;
        v[i] = *(const float2*)(W + (size_t)(k0 + k) * 3072 + (gate << 10) + j0 + 2 * q);
    }
}
__device__ __forceinline__ void sts_w(float* ws, const float2* v) {
    float4* w4p = (float4*)ws;
#pragma unroll
    for (int i = 0; i < 6; i++) {
        int idx  = i * NTHR + threadIdx.x;
        int k    = idx / 24, rem = idx - k * 24;
        int gate = rem >> 3;
        int q    = rem & 7;
        w4p[k * 24 + q * 3 + gate] = make_float4(v[i].x, v[i].x, v[i].y, v[i].y);
    }
}

// per-chunk compute, split-K x4: group g handles k in [g*32, g*32+32).
// thread = (jp, bq): 2 j-cols x 4 batch rows. acc[jj*2 + bu], lanes = (4bq+2bu, +1).
__device__ __forceinline__ void compute_chunk(const float* as, const float* ws,
                                              int g, int jp, int bq,
                                              ull* az, ull* ar, ull* ah) {
    const char* wb = (const char*)ws + jp * 48 + (size_t)g * 32 * 384;
    const char* ab = (const char*)as + bq * 16 + (size_t)g * 32 * 256;
#pragma unroll 8
    for (int k = 0; k < 32; k++) {
        ulonglong2 wz = *(const ulonglong2*)(wb + (size_t)k * 384);       // {dup wz_j, dup wz_j1}
        ulonglong2 wr = *(const ulonglong2*)(wb + (size_t)k * 384 + 16);
        ulonglong2 wh = *(const ulonglong2*)(wb + (size_t)k * 384 + 32);
        ulonglong2 a  = *(const ulonglong2*)(ab + (size_t)k * 256);       // {b0b1, b2b3}
        az[0] = fma2(a.x, wz.x, az[0]);  az[1] = fma2(a.y, wz.x, az[1]);
        az[2] = fma2(a.x, wz.y, az[2]);  az[3] = fma2(a.y, wz.y, az[3]);
        ar[0] = fma2(a.x, wr.x, ar[0]);  ar[1] = fma2(a.y, wr.x, ar[1]);
        ar[2] = fma2(a.x, wr.y, ar[2]);  ar[3] = fma2(a.y, wr.y, ar[3]);
        ah[0] = fma2(a.x, wh.x, ah[0]);  ah[1] = fma2(a.y, wh.x, ah[1]);
        ah[2] = fma2(a.x, wh.y, ah[2]);  ah[3] = fma2(a.y, wh.y, ah[3]);
    }
}

// double-buffered chunked GEMM accumulation over nch chunks of KC
__device__ __forceinline__ void gemm_phase(const float* abase, const float* __restrict__ W,
                                           int j0, int nch,
                                           float* as0, float* as1, float* ws0, float* ws1,
                                           int g, int jp, int bq,
                                           ull* az, ull* ar, ull* ah) {
    float2 v[6];
    ldg_w(W, 0, j0, v);
    sts_w(ws0, v);
    load_a(as0, abase);
    for (int c = 0; c < nch; c++) {
        float* ac = (c & 1) ? as1 : as0;
        float* wc = (c & 1) ? ws1 : ws0;
        if (c + 1 < nch) {
            float* an = (c & 1) ? as0 : as1;
            load_a(an, abase + (size_t)(c + 1) * KC * BB);
            ldg_w(W, (c + 1) * KC, j0, v);
            cp_wait1();
        } else {
            cp_wait0();
        }
        __syncthreads();
        compute_chunk(ac, wc, g, jp, bq, az, ar, ah);
        if (c + 1 < nch) {
            float* wn = (c & 1) ? ws0 : ws1;
            sts_w(wn, v);
        }
        __syncthreads();
    }
}

// ---------------- persistent recurrent kernel ----------------
__global__ void __launch_bounds__(NTHR, 1)
gru_kernel(const float* __restrict__ Wx_f, const float* __restrict__ Wh_f, const float* __restrict__ b_f,
           const float* __restrict__ Wx_b, const float* __restrict__ Wh_b, const float* __restrict__ b_b,
           float* __restrict__ out) {
    extern __shared__ char smem_raw[];
    float* as0 = (float*)smem_raw;                 // [KC][64]       32 KB
    float* as1 = as0 + KC * BB;                    //                32 KB
    float* ws0 = as1 + KC * BB;                    // [KC][8][48B]   48 KB (reduce scratch)
    float* ws1 = ws0 + KC * 96;                    //                48 KB
    ull*  maskS = (ull*)(ws1 + KC * 96);           // [TT]            4 KB

    const int bid = blockIdx.x, tid = threadIdx.x;
    const int d   = bid >> 6;                 // direction
    const int p   = bid & 63;                 // block within direction
    const int j0  = p << 4;                   // 16 j-columns per block
    const int g   = tid >> 7;                 // split-K group 0..3
    const int r   = tid & 127;
    const int w4  = r >> 5;                   // warp within group 0..3
    const int ln  = r & 31;
    const int jp  = (w4 & 1) * 4 + (ln >> 3); // 0..7
    const int bq  = (w4 >> 1) * 8 + (ln & 7); // 0..15
    // owned output quadrant = this thread's group id: jj = g>>1, bu = g&1
    const int jO  = j0 + 2 * jp + (g >> 1);
    const int bO  = 4 * bq + 2 * (g & 1);

    // stage mask bitmap (4 KB = 256 threads x 16B)
    if (tid < 256) cp16(maskS + tid * 2, g_maskB + tid * 2);
    cp_commit();

    const float* Wx   = d ? Wx_b : Wx_f;
    const float* Wh   = d ? Wh_b : Wh_f;
    const float* bias = d ? b_b  : b_f;
    const float bz = bias[jO]        + bias[3072 + jO];
    const float br = bias[1024 + jO] + bias[4096 + jO];
    const float bx = bias[2048 + jO];
    const float bh = bias[5120 + jO];

    // owned state: b = bO, bO+1 at column jO
    float hreg[2], oreg[2];
#pragma unroll
    for (int l = 0; l < 2; l++) {
        hreg[l] = g_Ht[d][0][jO * BB + bO + l];
        oreg[l] = 0.f;
    }

    // accumulators acc[jj*2 + bu]
    ull az[4], ar[4], axh[4], ahh[4];
#pragma unroll
    for (int i = 0; i < 4; i++) { az[i] = 0; ar[i] = 0; axh[i] = 0; ahh[i] = 0; }

    // x-part of step 0
    {
        int t0 = d ? (TT - 1) : 0;
        gemm_phase(g_Xt + (size_t)t0 * EE * BB, Wx, j0, EE / KC,
                   as0, as1, ws0, ws1, g, jp, bq, az, ar, axh);
    }

    for (int s = 0;; s++) {
        const int t   = d ? (TT - 1 - s) : s;
        const int par = s & 1;

        // recurrent part: hg += h @ Wh
        gemm_phase(g_Ht[d][par], Wh, j0, UU / KC,
                   as0, as1, ws0, ws1, g, jp, bq, az, ar, ahh);

        // ---- cross-group reduce via scratch on ws0 (dead: last chunk used ws1) ----
        // slot((owner q)*128 + r, contributor c): 4 ull {z, r, x, h}
        ull* red = (ull*)ws0;
#pragma unroll
        for (int q = 0; q < 4; q++) {
            if (q == g) continue;
            int c = g - (g > q ? 1 : 0);
            ull* dst = red + (size_t)(((q << 7) + r) * 3 + c) * 4;
            dst[0] = az[q]; dst[1] = ar[q]; dst[2] = axh[q]; dst[3] = ahh[q];
        }
        __syncthreads();

        ull sz = az[g], sr = ar[g], sx = axh[g], sh = ahh[g];
        {
            const ull* src = red + (size_t)(((g << 7) + r) * 3) * 4;
#pragma unroll
            for (int c = 0; c < 3; c++) {
                const ull* sp = src + c * 4;
                sz = add2(sz, sp[0]); sr = add2(sr, sp[1]);
                sx = add2(sx, sp[2]); sh = add2(sh, sp[3]);
            }
        }

        // ---- epilogue: gates, masking, writes (all 512 threads, 2 outputs each) ----
        {
            const ull mv = maskS[t];
            const size_t ocol = (size_t)t * 2048 + (size_t)d * UU + jO;
            float hv[2];
#pragma unroll
            for (int l = 0; l < 2; l++) {
                const bool m = (mv >> (bO + l)) & 1ull;
                float zs = l ? hi32(sz) : lo32(sz);
                float rs = l ? hi32(sr) : lo32(sr);
                float xs = l ? hi32(sx) : lo32(sx);
                float hs = l ? hi32(sh) : lo32(sh);
                float ez = __expf(-(zs + bz));
                float z  = __fdividef(1.f, 1.f + ez);
                float er = __expf(-(rs + br));
                float rg = __fdividef(1.f, 1.f + er);
                float hc = tanhf(xs + bx + rg * (hs + bh));
                float hn = z * hreg[l] + (1.f - z) * hc;
                hn = m ? hn : hreg[l];
                float o = m ? hn : oreg[l];
                hreg[l] = hn;
                oreg[l] = o;
                hv[l] = hn;
            }
            // publish h: STG.64 (owned batch pair contiguous)
            float* hdst = g_Ht[d][par ^ 1];
            *(float2*)&hdst[jO * BB + bO] = make_float2(hv[0], hv[1]);
            // outputs: 2 scalar STG.32
            out[(size_t)bO * (TT * 2048) + ocol]       = oreg[0];
            out[(size_t)(bO + 1) * (TT * 2048) + ocol] = oreg[1];
        }

        if (s == TT - 1) break;

        // arrive: h(s+1) published (sync also protects scratch before ws reuse)
        __syncthreads();
        if (tid == 0) { __threadfence(); atomicAdd(&g_count, 1u); }

        // zero accs; hide barrier latency with x-part of step s+1 (independent of h)
#pragma unroll
        for (int i = 0; i < 4; i++) { az[i] = 0; ar[i] = 0; axh[i] = 0; ahh[i] = 0; }
        {
            int tn = d ? (TT - 2 - s) : (s + 1);
            gemm_phase(g_Xt + (size_t)tn * EE * BB, Wx, j0, EE / KC,
                       as0, as1, ws0, ws1, g, jp, bq, az, ar, axh);
        }

        // wait: everyone published h(s+1)
        if (tid == 0) {
            unsigned tgt = (unsigned)(s + 1) * NB;
            volatile unsigned* pc = &g_count;
            while (*pc < tgt) { __nanosleep(32); }
            __threadfence();
        }
        __syncthreads();
    }

    // final state: [B, 2U] after the output block
    {
        const size_t STATE_OFF = (size_t)BB * TT * 2048;
#pragma unroll
        for (int l = 0; l < 2; l++)
            out[STATE_OFF + (size_t)(bO + l) * 2048 + (size_t)d * UU + jO] = hreg[l];
    }
}

// ---------------- launcher ----------------
extern "C" void kernel_launch(void* const* d_in, const int* in_sizes, int n_in,
                              void* d_out, int out_size) {
    (void)in_sizes; (void)n_in; (void)out_size;
    const int*   enc = (const int*)  d_in[0];
    const float* h0f = (const float*)d_in[1];
    const float* h0b = (const float*)d_in[2];
    const float* emb = (const float*)d_in[3];
    const float* Wxf = (const float*)d_in[4];
    const float* Whf = (const float*)d_in[5];
    const float* bf  = (const float*)d_in[6];
    const float* Wxb = (const float*)d_in[7];
    const float* Whb = (const float*)d_in[8];
    const float* bb  = (const float*)d_in[9];
    float* out = (float*)d_out;

    // 164 KB dynamic smem (> 113.5 KB) -> exactly ONE block per SM; all 128
    // persistent blocks land on distinct SMs (barrier-safe, no SM sharing).
    const int SMEM_BYTES = 164 * 1024;
    cudaFuncSetAttribute(gru_kernel, cudaFuncAttributeMaxDynamicSharedMemorySize, SMEM_BYTES);

    prep_kernel<<<TT, 256>>>(enc, emb);
    mask_kernel<<<2, 256>>>(enc);
    init_kernel<<<512, 256>>>(h0f, h0b);
    gru_kernel<<<NB, NTHR, SMEM_BYTES>>>(Wxf, Whf, bf, Wxb, Whb, bb, out);
}

// round 13
// speedup vs baseline: 1.3901x; 1.1843x over previous
#include <cuda_runtime.h>
#include <cstdint>

// Bidirectional GRU encoder: B=64, T=512, E=512, U=1024, gates (z,r,h), reset_after=True.
// out = [B,T,2U] outputs (fwd|bwd) followed by [B,2U] final state.
//
// v13: weights pre-duplicated in GMEM once (prep_w); per-chunk fills are TWO
// cp.async.bulk copies (w 48KB + a 32KB) with mbarrier completion, double-buffered,
// pipelined 2 chunks ahead. Compute core / reduce / epilogue identical to v11.

#define TT   512
#define BB   64
#define EE   512
#define UU   1024
#define KC   128
#define NB   128    // persistent blocks (64 per direction)
#define NTHR 512    // 4 warps/SMSP, 4 split-K groups

#define NCH_WH 8    // UU/KC
#define NCH_X  4    // EE/KC

#define WCH 12288                       // floats per duplicated w-chunk (KC*8jp*12)
#define ACH (KC * BB)                   // 8192 floats per a-chunk
#define BUFW_BYTES (WCH * 4)            // 49152
#define BUFA_BYTES (ACH * 4)            // 32768
#define BUF_BYTES  (BUFW_BYTES + BUFA_BYTES)   // 81920
#define RED_OFF    (2 * BUF_BYTES)             // 163840
#define MASK_OFF   (RED_OFF + 49152)           // 212992
#define MBAR_OFF   (MASK_OFF + 4096)           // 217088
#define SMEM_TOTAL (MBAR_OFF + 64)             // 217152  (<= 227KB, forces 1 block/SM)

typedef unsigned long long ull;

// ---------------- device scratch (static only — no cudaMalloc allowed) ----------------
__device__ __align__(16) float g_Xt[(size_t)TT * EE * BB];            // 64 MB
__device__ __align__(16) float g_Ht[2][2][UU * BB];                   // 1 MB
__device__ __align__(16) float g_Whd[(size_t)2 * 64 * NCH_WH * WCH];  // 50 MB dup Wh
__device__ __align__(16) float g_Wxd[(size_t)2 * 64 * NCH_X  * WCH];  // 25 MB dup Wx
__device__ __align__(16) ull   g_maskB[TT];
__device__ unsigned g_count;

// ---------------- helpers ----------------
__device__ __forceinline__ ull fma2(ull a, ull b, ull c) {
    ull d;
    asm("fma.rn.f32x2 %0, %1, %2, %3;" : "=l"(d) : "l"(a), "l"(b), "l"(c));
    return d;
}
__device__ __forceinline__ ull add2(ull a, ull b) {
    ull d;
    asm("add.rn.f32x2 %0, %1, %2;" : "=l"(d) : "l"(a), "l"(b));
    return d;
}
__device__ __forceinline__ float lo32(ull v) { return __uint_as_float((unsigned)v); }
__device__ __forceinline__ float hi32(ull v) { return __uint_as_float((unsigned)(v >> 32)); }

__device__ __forceinline__ unsigned smem_u32(const void* p) {
    return (unsigned)__cvta_generic_to_shared(p);
}
__device__ __forceinline__ void mb_init(unsigned a, unsigned n) {
    asm volatile("mbarrier.init.shared.b64 [%0], %1;" :: "r"(a), "r"(n) : "memory");
}
__device__ __forceinline__ void mb_expect(unsigned a, unsigned bytes) {
    asm volatile("mbarrier.arrive.expect_tx.shared.b64 _, [%0], %1;" :: "r"(a), "r"(bytes) : "memory");
}
__device__ __forceinline__ void bulk_g2s(unsigned dst, const void* src, unsigned bytes, unsigned mbar) {
    asm volatile("cp.async.bulk.shared::cluster.global.mbarrier::complete_tx::bytes [%0], [%1], %2, [%3];"
                 :: "r"(dst), "l"(src), "r"(bytes), "r"(mbar) : "memory");
}
__device__ __forceinline__ void mb_wait(unsigned a, unsigned ph) {
    asm volatile(
        "{\n\t"
        ".reg .pred P1;\n"
        "WAIT_LOOP_%=:\n\t"
        "mbarrier.try_wait.parity.acquire.cta.shared::cta.b64 P1, [%0], %1, 0x989680;\n\t"
        "@P1 bra.uni WAIT_DONE_%=;\n\t"
        "bra.uni WAIT_LOOP_%=;\n"
        "WAIT_DONE_%=:\n\t"
        "}" :: "r"(a), "r"(ph) : "memory");
}

// ---------------- prep: Xt[t][e][b] = emb[enc[b][t]][e] ----------------
__global__ void prep_kernel(const int* __restrict__ enc, const float* __restrict__ emb) {
    int t = blockIdx.x;
    __shared__ int tok[BB];
    if (threadIdx.x < BB) tok[threadIdx.x] = enc[threadIdx.x * TT + t];
    __syncthreads();
    for (int i = threadIdx.x; i < BB * (EE / 4); i += blockDim.x) {
        int e4 = i >> 6;
        int b  = i & 63;
        float4 v = *(const float4*)(emb + (size_t)tok[b] * EE + e4 * 4);
        size_t base = ((size_t)t * EE + (size_t)e4 * 4) * BB + b;
        g_Xt[base]          = v.x;
        g_Xt[base + BB]     = v.y;
        g_Xt[base + 2 * BB] = v.z;
        g_Xt[base + 3 * BB] = v.w;
    }
}

// ---------------- prep_w: duplicate weights into the smem-ready layout ----------------
// dst float index within a chunk: k*96 + q*12 + gate*4 + l ; value = W[(c*KC+k)*3072 + gate*1024 + p*16 + 2q + (l>>1)]
__global__ void prep_w_kernel(const float* __restrict__ W, int dir, int isX) {
    int c = blockIdx.x;     // chunk
    int p = blockIdx.y;     // j-tile (block of 16 j)
    int nch = isX ? NCH_X : NCH_WH;
    float* base = isX ? g_Wxd : g_Whd;
    float* o = base + (((size_t)dir * 64 + p) * nch + c) * WCH;
    for (int i = threadIdx.x; i < WCH; i += blockDim.x) {
        int k = i / 96;  int rem = i - k * 96;
        int q = rem / 12; int r2 = rem - q * 12;
        int gate = r2 >> 2; int l = r2 & 3;
        o[i] = W[(size_t)(c * KC + k) * 3072 + (gate << 10) + p * 16 + 2 * q + (l >> 1)];
    }
}

// ---------------- mask: pack enc!=0 into one uint64 per t ----------------
__global__ void mask_kernel(const int* __restrict__ enc) {
    int t = blockIdx.x * blockDim.x + threadIdx.x;
    if (t < TT) {
        ull m = 0;
        for (int b = 0; b < BB; b++)
            m |= (ull)(enc[b * TT + t] != 0) << b;
        g_maskB[t] = m;
    }
}

// ---------------- init: h0 -> g_Ht[dir][0]; reset barrier ----------------
__global__ void init_kernel(const float* __restrict__ h0f, const float* __restrict__ h0b) {
    int i = blockIdx.x * blockDim.x + threadIdx.x;  // 0 .. 131071
    if (i == 0) g_count = 0u;
    int d = i >> 16;
    int r = i & 65535;
    int u = r >> 6;
    int b = r & 63;
    const float* h0 = d ? h0b : h0f;
    g_Ht[d][0][u * BB + b] = h0[b * UU + u];
}

// ---------------- per-chunk compute (identical to v11) ----------------
// split-K x4: group g handles k in [g*32, g*32+32). thread = (jp, bq): 2j x 4b.
__device__ __forceinline__ void compute_chunk(const float* as, const float* ws,
                                              int g, int jp, int bq,
                                              ull* az, ull* ar, ull* ah) {
    const char* wb = (const char*)ws + jp * 48 + (size_t)g * 32 * 384;
    const char* ab = (const char*)as + bq * 16 + (size_t)g * 32 * 256;
#pragma unroll 8
    for (int k = 0; k < 32; k++) {
        ulonglong2 wz = *(const ulonglong2*)(wb + (size_t)k * 384);
        ulonglong2 wr = *(const ulonglong2*)(wb + (size_t)k * 384 + 16);
        ulonglong2 wh = *(const ulonglong2*)(wb + (size_t)k * 384 + 32);
        ulonglong2 a  = *(const ulonglong2*)(ab + (size_t)k * 256);
        az[0] = fma2(a.x, wz.x, az[0]);  az[1] = fma2(a.y, wz.x, az[1]);
        az[2] = fma2(a.x, wz.y, az[2]);  az[3] = fma2(a.y, wz.y, az[3]);
        ar[0] = fma2(a.x, wr.x, ar[0]);  ar[1] = fma2(a.y, wr.x, ar[1]);
        ar[2] = fma2(a.x, wr.y, ar[2]);  ar[3] = fma2(a.y, wr.y, ar[3]);
        ah[0] = fma2(a.x, wh.x, ah[0]);  ah[1] = fma2(a.y, wh.x, ah[1]);
        ah[2] = fma2(a.x, wh.y, ah[2]);  ah[3] = fma2(a.y, wh.y, ah[3]);
    }
}

// ---------------- persistent recurrent kernel ----------------
__global__ void __launch_bounds__(NTHR, 1)
gru_kernel(const float* __restrict__ b_f, const float* __restrict__ b_b,
           float* __restrict__ out) {
    extern __shared__ __align__(128) char smem[];
    const unsigned smb = smem_u32(smem);
    ull*  redp  = (ull*)(smem + RED_OFF);
    ull*  maskS = (ull*)(smem + MASK_OFF);

    const int bid = blockIdx.x, tid = threadIdx.x;
    const int d   = bid >> 6;
    const int p   = bid & 63;
    const int g   = tid >> 7;                 // split-K group 0..3
    const int r   = tid & 127;
    const int w4  = r >> 5;
    const int ln  = r & 31;
    const int jp  = (w4 & 1) * 4 + (ln >> 3);
    const int bq  = (w4 >> 1) * 8 + (ln & 7);
    const int j0  = p << 4;
    const int jO  = j0 + 2 * jp + (g >> 1);   // owned column
    const int bO  = 4 * bq + 2 * (g & 1);     // owned batch pair

    // mbarriers + mask staging
    if (tid == 0) { mb_init(smb + MBAR_OFF, 1); mb_init(smb + MBAR_OFF + 8, 1); }
    for (int i = tid; i < TT; i += NTHR) maskS[i] = g_maskB[i];
    __syncthreads();

    const float* whd = g_Whd + ((size_t)(d * 64 + p)) * NCH_WH * WCH;
    const float* wxd = g_Wxd + ((size_t)(d * 64 + p)) * NCH_X  * WCH;

    const float* bias = d ? b_b : b_f;
    const float bz = bias[jO]        + bias[3072 + jO];
    const float br = bias[1024 + jO] + bias[4096 + jO];
    const float bx = bias[2048 + jO];
    const float bh = bias[5120 + jO];

    float hreg[2], oreg[2];
#pragma unroll
    for (int l = 0; l < 2; l++) {
        hreg[l] = g_Ht[d][0][jO * BB + bO + l];
        oreg[l] = 0.f;
    }

    ull az[4], ar[4], axh[4], ahh[4];
#pragma unroll
    for (int i = 0; i < 4; i++) { az[i] = 0; ar[i] = 0; axh[i] = 0; ahh[i] = 0; }

    unsigned fc = 0, cc = 0;   // fill / consume counters (uniform across threads)

    // fill helper semantics: buffer = fc&1, then fc++
#define DO_FILL(WSRC, ASRC)                                                    \
    do {                                                                       \
        if (tid == 0) {                                                        \
            unsigned _b   = fc & 1;                                            \
            unsigned _dst = smb + _b * BUF_BYTES;                              \
            unsigned _mb  = smb + MBAR_OFF + _b * 8;                           \
            mb_expect(_mb, BUF_BYTES);                                         \
            bulk_g2s(_dst, (WSRC), BUFW_BYTES, _mb);                           \
            bulk_g2s(_dst + BUFW_BYTES, (ASRC), BUFA_BYTES, _mb);              \
        }                                                                      \
        fc++;                                                                  \
    } while (0)

#define WAIT_BUF(WS, AS)                                                       \
    do {                                                                       \
        unsigned _b = cc & 1;                                                  \
        mb_wait(smb + MBAR_OFF + _b * 8, (cc >> 1) & 1);                       \
        (WS) = (const float*)(smem + _b * BUF_BYTES);                          \
        (AS) = (const float*)(smem + _b * BUF_BYTES + BUFW_BYTES);             \
    } while (0)

    // ---- prologue: X phase of step 0 ----
    {
        const int t0 = d ? (TT - 1) : 0;
        const float* xa = g_Xt + (size_t)t0 * EE * BB;
        DO_FILL(wxd, xa);
        DO_FILL(wxd + WCH, xa + ACH);
        for (int c = 0; c < NCH_X; c++) {
            const float *ws, *as;
            WAIT_BUF(ws, as);
            compute_chunk(as, ws, g, jp, bq, az, ar, axh);
            __syncthreads();
            if (c < 2) DO_FILL(wxd + (c + 2) * WCH, xa + (size_t)(c + 2) * ACH);
            else       DO_FILL(whd + (c - 2) * WCH, g_Ht[d][0] + (size_t)(c - 2) * ACH);
            cc++;
        }
    }

    for (int s = 0;; s++) {
        const int t   = d ? (TT - 1 - s) : s;
        const int par = s & 1;
        const float* ha = g_Ht[d][par];

        // ---- Wh phase: 8 chunks (fills for 0,1 already in flight) ----
        for (int c = 0; c < NCH_WH; c++) {
            const float *ws, *as;
            WAIT_BUF(ws, as);
            compute_chunk(as, ws, g, jp, bq, az, ar, ahh);
            __syncthreads();
            if (c < 6) {
                DO_FILL(whd + (c + 2) * WCH, ha + (size_t)(c + 2) * ACH);
            } else if (s < TT - 1) {
                const int tn = d ? (TT - 2 - s) : (s + 1);
                DO_FILL(wxd + (c - 6) * WCH,
                        g_Xt + (size_t)tn * EE * BB + (size_t)(c - 6) * ACH);
            }
            cc++;
        }

        // ---- cross-group reduce via dedicated scratch ----
#pragma unroll
        for (int q = 0; q < 4; q++) {
            if (q == g) continue;
            int c2 = g - (g > q ? 1 : 0);
            ull* dst = redp + (size_t)(((q << 7) + r) * 3 + c2) * 4;
            dst[0] = az[q]; dst[1] = ar[q]; dst[2] = axh[q]; dst[3] = ahh[q];
        }
        __syncthreads();

        ull sz = az[g], sr = ar[g], sx = axh[g], sh = ahh[g];
        {
            const ull* src = redp + (size_t)(((g << 7) + r) * 3) * 4;
#pragma unroll
            for (int c2 = 0; c2 < 3; c2++) {
                const ull* sp = src + c2 * 4;
                sz = add2(sz, sp[0]); sr = add2(sr, sp[1]);
                sx = add2(sx, sp[2]); sh = add2(sh, sp[3]);
            }
        }

        // ---- epilogue: gates, masking, writes ----
        {
            const ull mv = maskS[t];
            const size_t ocol = (size_t)t * 2048 + (size_t)d * UU + jO;
            float hv[2];
#pragma unroll
            for (int l = 0; l < 2; l++) {
                const bool m = (mv >> (bO + l)) & 1ull;
                float zs = l ? hi32(sz) : lo32(sz);
                float rs = l ? hi32(sr) : lo32(sr);
                float xs = l ? hi32(sx) : lo32(sx);
                float hs = l ? hi32(sh) : lo32(sh);
                float ez = __expf(-(zs + bz));
                float z  = __fdividef(1.f, 1.f + ez);
                float er = __expf(-(rs + br));
                float rg = __fdividef(1.f, 1.f + er);
                float hc = tanhf(xs + bx + rg * (hs + bh));
                float hn = z * hreg[l] + (1.f - z) * hc;
                hn = m ? hn : hreg[l];
                float o = m ? hn : oreg[l];
                hreg[l] = hn;
                oreg[l] = o;
                hv[l] = hn;
            }
            float* hdst = g_Ht[d][par ^ 1];
            *(float2*)&hdst[jO * BB + bO] = make_float2(hv[0], hv[1]);
            out[(size_t)bO * (TT * 2048) + ocol]       = oreg[0];
            out[(size_t)(bO + 1) * (TT * 2048) + ocol] = oreg[1];
        }

        if (s == TT - 1) break;

        // ---- arrive: h(s+1) published ----
        __syncthreads();
        if (tid == 0) { __threadfence(); atomicAdd(&g_count, 1u); }

        // zero accs; X phase for step s+1 (fills X0,X1 already in flight)
#pragma unroll
        for (int i = 0; i < 4; i++) { az[i] = 0; ar[i] = 0; axh[i] = 0; ahh[i] = 0; }
        {
            const int tn = d ? (TT - 2 - s) : (s + 1);
            const float* xa = g_Xt + (size_t)tn * EE * BB;
            for (int c = 0; c < NCH_X; c++) {
                const float *ws, *as;
                WAIT_BUF(ws, as);
                compute_chunk(as, ws, g, jp, bq, az, ar, axh);
                __syncthreads();
                if (c < 2) DO_FILL(wxd + (c + 2) * WCH, xa + (size_t)(c + 2) * ACH);
                cc++;
            }
        }

        // ---- wait: everyone published h(s+1) ----
        if (tid == 0) {
            unsigned tgt = (unsigned)(s + 1) * NB;
            volatile unsigned* pc = &g_count;
            while (*pc < tgt) { __nanosleep(32); }
            __threadfence();
        }
        __syncthreads();

        // fills for next step's Wh0, Wh1 (h(s+1) now globally visible)
        {
            const float* han = g_Ht[d][par ^ 1];
            DO_FILL(whd, han);
            DO_FILL(whd + WCH, han + ACH);
        }
    }

    // final state: [B, 2U] after the output block
    {
        const size_t STATE_OFF = (size_t)BB * TT * 2048;
#pragma unroll
        for (int l = 0; l < 2; l++)
            out[STATE_OFF + (size_t)(bO + l) * 2048 + (size_t)d * UU + jO] = hreg[l];
    }
#undef DO_FILL
#undef WAIT_BUF
}

// ---------------- launcher ----------------
extern "C" void kernel_launch(void* const* d_in, const int* in_sizes, int n_in,
                              void* d_out, int out_size) {
    (void)in_sizes; (void)n_in; (void)out_size;
    const int*   enc = (const int*)  d_in[0];
    const float* h0f = (const float*)d_in[1];
    const float* h0b = (const float*)d_in[2];
    const float* emb = (const float*)d_in[3];
    const float* Wxf = (const float*)d_in[4];
    const float* Whf = (const float*)d_in[5];
    const float* bf  = (const float*)d_in[6];
    const float* Wxb = (const float*)d_in[7];
    const float* Whb = (const float*)d_in[8];
    const float* bb  = (const float*)d_in[9];
    float* out = (float*)d_out;

    cudaFuncSetAttribute(gru_kernel, cudaFuncAttributeMaxDynamicSharedMemorySize, SMEM_TOTAL);

    prep_kernel<<<TT, 256>>>(enc, emb);
    prep_w_kernel<<<dim3(NCH_WH, 64), 256>>>(Whf, 0, 0);
    prep_w_kernel<<<dim3(NCH_WH, 64), 256>>>(Whb, 1, 0);
    prep_w_kernel<<<dim3(NCH_X, 64), 256>>>(Wxf, 0, 1);
    prep_w_kernel<<<dim3(NCH_X, 64), 256>>>(Wxb, 1, 1);
    mask_kernel<<<2, 256>>>(enc);
    init_kernel<<<512, 256>>>(h0f, h0b);
    gru_kernel<<<NB, NTHR, SMEM_TOTAL>>>(bf, bb, out);
}

// round 15
// speedup vs baseline: 1.3929x; 1.0020x over previous
#include <cuda_runtime.h>
#include <cstdint>

// Bidirectional GRU encoder: B=64, T=512, E=512, U=1024, gates (z,r,h), reset_after=True.
// out = [B,T,2U] outputs (fwd|bwd) followed by [B,2U] final state.
//
// v15 = v13 + gate-major duplicated-weight layout ([k][gate][q][4]): a warp's 4 jp
// slots are contiguous 64B -> every weight LDS.128 is ONE wavefront (was two).
// Per-SM wavefronts/chunk drop 3584 -> 2048, putting FMA (3072 cyc/chunk) in charge.

#define TT   512
#define BB   64
#define EE   512
#define UU   1024
#define KC   128
#define NB   128    // persistent blocks (64 per direction)
#define NTHR 512    // 4 warps/SMSP, 4 split-K groups

#define NCH_WH 8    // UU/KC
#define NCH_X  4    // EE/KC

#define WCH 12288                       // floats per duplicated w-chunk (KC*96)
#define ACH (KC * BB)                   // 8192 floats per a-chunk
#define BUFW_BYTES (WCH * 4)            // 49152
#define BUFA_BYTES (ACH * 4)            // 32768
#define BUF_BYTES  (BUFW_BYTES + BUFA_BYTES)   // 81920
#define RED_OFF    (2 * BUF_BYTES)             // 163840
#define MASK_OFF   (RED_OFF + 49152)           // 212992
#define MBAR_OFF   (MASK_OFF + 4096)           // 217088
#define SMEM_TOTAL (MBAR_OFF + 64)             // 217152  (forces 1 block/SM)

typedef unsigned long long ull;

// ---------------- device scratch (static only — no cudaMalloc allowed) ----------------
__device__ __align__(16) float g_Xt[(size_t)TT * EE * BB];            // 64 MB
__device__ __align__(16) float g_Ht[2][2][UU * BB];                   // 1 MB
__device__ __align__(16) float g_Whd[(size_t)2 * 64 * NCH_WH * WCH];  // 50 MB dup Wh
__device__ __align__(16) float g_Wxd[(size_t)2 * 64 * NCH_X  * WCH];  // 25 MB dup Wx
__device__ __align__(16) ull   g_maskB[TT];
__device__ unsigned g_count;

// ---------------- helpers ----------------
__device__ __forceinline__ ull fma2(ull a, ull b, ull c) {
    ull d;
    asm("fma.rn.f32x2 %0, %1, %2, %3;" : "=l"(d) : "l"(a), "l"(b), "l"(c));
    return d;
}
__device__ __forceinline__ ull add2(ull a, ull b) {
    ull d;
    asm("add.rn.f32x2 %0, %1, %2;" : "=l"(d) : "l"(a), "l"(b));
    return d;
}
__device__ __forceinline__ float lo32(ull v) { return __uint_as_float((unsigned)v); }
__device__ __forceinline__ float hi32(ull v) { return __uint_as_float((unsigned)(v >> 32)); }

__device__ __forceinline__ unsigned smem_u32(const void* p) {
    return (unsigned)__cvta_generic_to_shared(p);
}
__device__ __forceinline__ void mb_init(unsigned a, unsigned n) {
    asm volatile("mbarrier.init.shared.b64 [%0], %1;" :: "r"(a), "r"(n) : "memory");
}
__device__ __forceinline__ void mb_expect(unsigned a, unsigned bytes) {
    asm volatile("mbarrier.arrive.expect_tx.shared.b64 _, [%0], %1;" :: "r"(a), "r"(bytes) : "memory");
}
__device__ __forceinline__ void bulk_g2s(unsigned dst, const void* src, unsigned bytes, unsigned mbar) {
    asm volatile("cp.async.bulk.shared::cluster.global.mbarrier::complete_tx::bytes [%0], [%1], %2, [%3];"
                 :: "r"(dst), "l"(src), "r"(bytes), "r"(mbar) : "memory");
}
__device__ __forceinline__ void mb_wait(unsigned a, unsigned ph) {
    asm volatile(
        "{\n\t"
        ".reg .pred P1;\n"
        "WAIT_LOOP_%=:\n\t"
        "mbarrier.try_wait.parity.acquire.cta.shared::cta.b64 P1, [%0], %1, 0x989680;\n\t"
        "@P1 bra.uni WAIT_DONE_%=;\n\t"
        "bra.uni WAIT_LOOP_%=;\n"
        "WAIT_DONE_%=:\n\t"
        "}" :: "r"(a), "r"(ph) : "memory");
}

// ---------------- prep: Xt[t][e][b] = emb[enc[b][t]][e] ----------------
__global__ void prep_kernel(const int* __restrict__ enc, const float* __restrict__ emb) {
    int t = blockIdx.x;
    __shared__ int tok[BB];
    if (threadIdx.x < BB) tok[threadIdx.x] = enc[threadIdx.x * TT + t];
    __syncthreads();
    for (int i = threadIdx.x; i < BB * (EE / 4); i += blockDim.x) {
        int e4 = i >> 6;
        int b  = i & 63;
        float4 v = *(const float4*)(emb + (size_t)tok[b] * EE + e4 * 4);
        size_t base = ((size_t)t * EE + (size_t)e4 * 4) * BB + b;
        g_Xt[base]          = v.x;
        g_Xt[base + BB]     = v.y;
        g_Xt[base + 2 * BB] = v.z;
        g_Xt[base + 3 * BB] = v.w;
    }
}

// ---------------- prep_w: duplicate weights into gate-major smem-ready layout ----------
// dst float index within a chunk: k*96 + gate*32 + q*4 + l
// value = W[(c*KC+k)*3072 + gate*1024 + p*16 + 2q + (l>>1)]   (l = dup lane: 0,1->j ; 2,3->j+1)
__global__ void prep_w_kernel(const float* __restrict__ W, int dir, int isX) {
    int c = blockIdx.x;     // chunk
    int p = blockIdx.y;     // j-tile (block of 16 j)
    int nch = isX ? NCH_X : NCH_WH;
    float* base = isX ? g_Wxd : g_Whd;
    float* o = base + (((size_t)dir * 64 + p) * nch + c) * WCH;
    for (int i = threadIdx.x; i < WCH; i += blockDim.x) {
        int k = i / 96;   int rem = i - k * 96;
        int gate = rem >> 5;  int r2 = rem & 31;
        int q = r2 >> 2;  int l = r2 & 3;
        o[i] = W[(size_t)(c * KC + k) * 3072 + (gate << 10) + p * 16 + 2 * q + (l >> 1)];
    }
}

// ---------------- mask: pack enc!=0 into one uint64 per t ----------------
__global__ void mask_kernel(const int* __restrict__ enc) {
    int t = blockIdx.x * blockDim.x + threadIdx.x;
    if (t < TT) {
        ull m = 0;
        for (int b = 0; b < BB; b++)
            m |= (ull)(enc[b * TT + t] != 0) << b;
        g_maskB[t] = m;
    }
}

// ---------------- init: h0 -> g_Ht[dir][0]; reset barrier ----------------
__global__ void init_kernel(const float* __restrict__ h0f, const float* __restrict__ h0b) {
    int i = blockIdx.x * blockDim.x + threadIdx.x;  // 0 .. 131071
    if (i == 0) g_count = 0u;
    int d = i >> 16;
    int r = i & 65535;
    int u = r >> 6;
    int b = r & 63;
    const float* h0 = d ? h0b : h0f;
    g_Ht[d][0][u * BB + b] = h0[b * UU + u];
}

// ---------------- per-chunk compute ----------------
// split-K x4: group g handles k in [g*32, g*32+32). thread = (jp, bq): 2j x 4b.
// ws layout: [k][gate][q][4 floats]; warp's 4 jp slots contiguous -> 1 wf per weight LDS.
__device__ __forceinline__ void compute_chunk(const float* as, const float* ws,
                                              int g, int jp, int bq,
                                              ull* az, ull* ar, ull* ah) {
    const char* wb = (const char*)ws + jp * 16 + (size_t)g * 32 * 384;
    const char* ab = (const char*)as + bq * 16 + (size_t)g * 32 * 256;
#pragma unroll 8
    for (int k = 0; k < 32; k++) {
        ulonglong2 wz = *(const ulonglong2*)(wb + (size_t)k * 384);
        ulonglong2 wr = *(const ulonglong2*)(wb + (size_t)k * 384 + 128);
        ulonglong2 wh = *(const ulonglong2*)(wb + (size_t)k * 384 + 256);
        ulonglong2 a  = *(const ulonglong2*)(ab + (size_t)k * 256);
        az[0] = fma2(a.x, wz.x, az[0]);  az[1] = fma2(a.y, wz.x, az[1]);
        az[2] = fma2(a.x, wz.y, az[2]);  az[3] = fma2(a.y, wz.y, az[3]);
        ar[0] = fma2(a.x, wr.x, ar[0]);  ar[1] = fma2(a.y, wr.x, ar[1]);
        ar[2] = fma2(a.x, wr.y, ar[2]);  ar[3] = fma2(a.y, wr.y, ar[3]);
        ah[0] = fma2(a.x, wh.x, ah[0]);  ah[1] = fma2(a.y, wh.x, ah[1]);
        ah[2] = fma2(a.x, wh.y, ah[2]);  ah[3] = fma2(a.y, wh.y, ah[3]);
    }
}

// ---------------- persistent recurrent kernel ----------------
__global__ void __launch_bounds__(NTHR, 1)
gru_kernel(const float* __restrict__ b_f, const float* __restrict__ b_b,
           float* __restrict__ out) {
    extern __shared__ __align__(128) char smem[];
    const unsigned smb = smem_u32(smem);
    ull*  redp  = (ull*)(smem + RED_OFF);
    ull*  maskS = (ull*)(smem + MASK_OFF);

    const int bid = blockIdx.x, tid = threadIdx.x;
    const int d   = bid >> 6;
    const int p   = bid & 63;
    const int g   = tid >> 7;                 // split-K group 0..3
    const int r   = tid & 127;
    const int w4  = r >> 5;
    const int ln  = r & 31;
    const int jp  = (w4 & 1) * 4 + (ln >> 3);
    const int bq  = (w4 >> 1) * 8 + (ln & 7);
    const int j0  = p << 4;
    const int jO  = j0 + 2 * jp + (g >> 1);   // owned column
    const int bO  = 4 * bq + 2 * (g & 1);     // owned batch pair

    // mbarriers + mask staging
    if (tid == 0) { mb_init(smb + MBAR_OFF, 1); mb_init(smb + MBAR_OFF + 8, 1); }
    for (int i = tid; i < TT; i += NTHR) maskS[i] = g_maskB[i];
    __syncthreads();

    const float* whd = g_Whd + ((size_t)(d * 64 + p)) * NCH_WH * WCH;
    const float* wxd = g_Wxd + ((size_t)(d * 64 + p)) * NCH_X  * WCH;

    const float* bias = d ? b_b : b_f;
    const float bz = bias[jO]        + bias[3072 + jO];
    const float br = bias[1024 + jO] + bias[4096 + jO];
    const float bx = bias[2048 + jO];
    const float bh = bias[5120 + jO];

    float hreg[2], oreg[2];
#pragma unroll
    for (int l = 0; l < 2; l++) {
        hreg[l] = g_Ht[d][0][jO * BB + bO + l];
        oreg[l] = 0.f;
    }

    ull az[4], ar[4], axh[4], ahh[4];
#pragma unroll
    for (int i = 0; i < 4; i++) { az[i] = 0; ar[i] = 0; axh[i] = 0; ahh[i] = 0; }

    unsigned fc = 0, cc = 0;   // fill / consume counters (uniform across threads)

#define DO_FILL(WSRC, ASRC)                                                    \
    do {                                                                       \
        if (tid == 0) {                                                        \
            unsigned _b   = fc & 1;                                            \
            unsigned _dst = smb + _b * BUF_BYTES;                              \
            unsigned _mb  = smb + MBAR_OFF + _b * 8;                           \
            mb_expect(_mb, BUF_BYTES);                                         \
            bulk_g2s(_dst, (WSRC), BUFW_BYTES, _mb);                           \
            bulk_g2s(_dst + BUFW_BYTES, (ASRC), BUFA_BYTES, _mb);              \
        }                                                                      \
        fc++;                                                                  \
    } while (0)

#define WAIT_BUF(WS, AS)                                                       \
    do {                                                                       \
        unsigned _b = cc & 1;                                                  \
        mb_wait(smb + MBAR_OFF + _b * 8, (cc >> 1) & 1);                       \
        (WS) = (const float*)(smem + _b * BUF_BYTES);                          \
        (AS) = (const float*)(smem + _b * BUF_BYTES + BUFW_BYTES);             \
    } while (0)

    // ---- prologue: X phase of step 0 ----
    {
        const int t0 = d ? (TT - 1) : 0;
        const float* xa = g_Xt + (size_t)t0 * EE * BB;
        DO_FILL(wxd, xa);
        DO_FILL(wxd + WCH, xa + ACH);
        for (int c = 0; c < NCH_X; c++) {
            const float *ws, *as;
            WAIT_BUF(ws, as);
            compute_chunk(as, ws, g, jp, bq, az, ar, axh);
            __syncthreads();
            if (c < 2) DO_FILL(wxd + (c + 2) * WCH, xa + (size_t)(c + 2) * ACH);
            else       DO_FILL(whd + (c - 2) * WCH, g_Ht[d][0] + (size_t)(c - 2) * ACH);
            cc++;
        }
    }

    for (int s = 0;; s++) {
        const int t   = d ? (TT - 1 - s) : s;
        const int par = s & 1;
        const float* ha = g_Ht[d][par];

        // ---- Wh phase: 8 chunks (fills for 0,1 already in flight) ----
        for (int c = 0; c < NCH_WH; c++) {
            const float *ws, *as;
            WAIT_BUF(ws, as);
            compute_chunk(as, ws, g, jp, bq, az, ar, ahh);
            __syncthreads();
            if (c < 6) {
                DO_FILL(whd + (c + 2) * WCH, ha + (size_t)(c + 2) * ACH);
            } else if (s < TT - 1) {
                const int tn = d ? (TT - 2 - s) : (s + 1);
                DO_FILL(wxd + (c - 6) * WCH,
                        g_Xt + (size_t)tn * EE * BB + (size_t)(c - 6) * ACH);
            }
            cc++;
        }

        // ---- cross-group reduce via dedicated scratch ----
#pragma unroll
        for (int q = 0; q < 4; q++) {
            if (q == g) continue;
            int c2 = g - (g > q ? 1 : 0);
            ull* dst = redp + (size_t)(((q << 7) + r) * 3 + c2) * 4;
            dst[0] = az[q]; dst[1] = ar[q]; dst[2] = axh[q]; dst[3] = ahh[q];
        }
        __syncthreads();

        ull sz = az[g], sr = ar[g], sx = axh[g], sh = ahh[g];
        {
            const ull* src = redp + (size_t)(((g << 7) + r) * 3) * 4;
#pragma unroll
            for (int c2 = 0; c2 < 3; c2++) {
                const ull* sp = src + c2 * 4;
                sz = add2(sz, sp[0]); sr = add2(sr, sp[1]);
                sx = add2(sx, sp[2]); sh = add2(sh, sp[3]);
            }
        }

        // ---- epilogue: gates, masking, writes ----
        {
            const ull mv = maskS[t];
            const size_t ocol = (size_t)t * 2048 + (size_t)d * UU + jO;
            float hv[2];
#pragma unroll
            for (int l = 0; l < 2; l++) {
                const bool m = (mv >> (bO + l)) & 1ull;
                float zs = l ? hi32(sz) : lo32(sz);
                float rs = l ? hi32(sr) : lo32(sr);
                float xs = l ? hi32(sx) : lo32(sx);
                float hs = l ? hi32(sh) : lo32(sh);
                float ez = __expf(-(zs + bz));
                float z  = __fdividef(1.f, 1.f + ez);
                float er = __expf(-(rs + br));
                float rg = __fdividef(1.f, 1.f + er);
                float hc = tanhf(xs + bx + rg * (hs + bh));
                float hn = z * hreg[l] + (1.f - z) * hc;
                hn = m ? hn : hreg[l];
                float o = m ? hn : oreg[l];
                hreg[l] = hn;
                oreg[l] = o;
                hv[l] = hn;
            }
            float* hdst = g_Ht[d][par ^ 1];
            *(float2*)&hdst[jO * BB + bO] = make_float2(hv[0], hv[1]);
            out[(size_t)bO * (TT * 2048) + ocol]       = oreg[0];
            out[(size_t)(bO + 1) * (TT * 2048) + ocol] = oreg[1];
        }

        if (s == TT - 1) break;

        // ---- arrive: h(s+1) published ----
        __syncthreads();
        if (tid == 0) { __threadfence(); atomicAdd(&g_count, 1u); }

        // zero accs; X phase for step s+1 (fills X0,X1 already in flight)
#pragma unroll
        for (int i = 0; i < 4; i++) { az[i] = 0; ar[i] = 0; axh[i] = 0; ahh[i] = 0; }
        {
            const int tn = d ? (TT - 2 - s) : (s + 1);
            const float* xa = g_Xt + (size_t)tn * EE * BB;
            for (int c = 0; c < NCH_X; c++) {
                const float *ws, *as;
                WAIT_BUF(ws, as);
                compute_chunk(as, ws, g, jp, bq, az, ar, axh);
                __syncthreads();
                if (c < 2) DO_FILL(wxd + (c + 2) * WCH, xa + (size_t)(c + 2) * ACH);
                cc++;
            }
        }

        // ---- wait: everyone published h(s+1) ----
        if (tid == 0) {
            unsigned tgt = (unsigned)(s + 1) * NB;
            volatile unsigned* pc = &g_count;
            while (*pc < tgt) { __nanosleep(32); }
            __threadfence();
        }
        __syncthreads();

        // fills for next step's Wh0, Wh1 (h(s+1) now globally visible)
        {
            const float* han = g_Ht[d][par ^ 1];
            DO_FILL(whd, han);
            DO_FILL(whd + WCH, han + ACH);
        }
    }

    // final state: [B, 2U] after the output block
    {
        const size_t STATE_OFF = (size_t)BB * TT * 2048;
#pragma unroll
        for (int l = 0; l < 2; l++)
            out[STATE_OFF + (size_t)(bO + l) * 2048 + (size_t)d * UU + jO] = hreg[l];
    }
#undef DO_FILL
#undef WAIT_BUF
}

// ---------------- launcher ----------------
extern "C" void kernel_launch(void* const* d_in, const int* in_sizes, int n_in,
                              void* d_out, int out_size) {
    (void)in_sizes; (void)n_in; (void)out_size;
    const int*   enc = (const int*)  d_in[0];
    const float* h0f = (const float*)d_in[1];
    const float* h0b = (const float*)d_in[2];
    const float* emb = (const float*)d_in[3];
    const float* Wxf = (const float*)d_in[4];
    const float* Whf = (const float*)d_in[5];
    const float* bf  = (const float*)d_in[6];
    const float* Wxb = (const float*)d_in[7];
    const float* Whb = (const float*)d_in[8];
    const float* bb  = (const float*)d_in[9];
    float* out = (float*)d_out;

    cudaFuncSetAttribute(gru_kernel, cudaFuncAttributeMaxDynamicSharedMemorySize, SMEM_TOTAL);

    prep_kernel<<<TT, 256>>>(enc, emb);
    prep_w_kernel<<<dim3(NCH_WH, 64), 256>>>(Whf, 0, 0);
    prep_w_kernel<<<dim3(NCH_WH, 64), 256>>>(Whb, 1, 0);
    prep_w_kernel<<<dim3(NCH_X, 64), 256>>>(Wxf, 0, 1);
    prep_w_kernel<<<dim3(NCH_X, 64), 256>>>(Wxb, 1, 1);
    mask_kernel<<<2, 256>>>(enc);
    init_kernel<<<512, 256>>>(h0f, h0b);
    gru_kernel<<<NB, NTHR, SMEM_TOTAL>>>(bf, bb, out);
}

// round 16
// speedup vs baseline: 1.5695x; 1.1267x over previous
#include <cuda_runtime.h>
#include <cstdint>

// Bidirectional GRU encoder: B=64, T=512, E=512, U=1024, gates (z,r,h), reset_after=True.
// out = [B,T,2U] outputs (fwd|bwd) followed by [B,2U] final state.
//
// v16 = v15 compute core + warp-specialized producer (warp 16) driving a full/empty
// mbarrier ring (no __syncthreads in the chunk loop) + fine-grained per-u-chunk h
// counters replacing the monolithic global barrier.

#define TT   512
#define BB   64
#define EE   512
#define UU   1024
#define KC   128
#define NB   128    // persistent blocks (64 per direction)
#define NTHR 544    // 512 compute (16 warps) + 32 producer (warp 16)

#define NCH_WH 8    // UU/KC
#define NCH_X  4    // EE/KC

#define WCH 12288                       // floats per duplicated w-chunk (KC*96)
#define ACH (KC * BB)                   // 8192 floats per a-chunk
#define BUFW_BYTES (WCH * 4)            // 49152
#define BUFA_BYTES (ACH * 4)            // 32768
#define BUF_BYTES  (BUFW_BYTES + BUFA_BYTES)   // 81920
#define RED_OFF    (2 * BUF_BYTES)             // 163840
#define MASK_OFF   (RED_OFF + 49152)           // 212992
#define MBAR_OFF   (MASK_OFF + 4096)           // 217088: full0,full1,empty0,empty1
#define SMEM_TOTAL (MBAR_OFF + 64)             // 217152 (forces 1 block/SM)

typedef unsigned long long ull;

// ---------------- device scratch (static only — no cudaMalloc allowed) ----------------
__device__ __align__(16) float g_Xt[(size_t)TT * EE * BB];            // 64 MB
__device__ __align__(16) float g_Ht[2][2][UU * BB];                   // 1 MB
__device__ __align__(16) float g_Whd[(size_t)2 * 64 * NCH_WH * WCH];  // 50 MB dup Wh
__device__ __align__(16) float g_Wxd[(size_t)2 * 64 * NCH_X  * WCH];  // 25 MB dup Wx
__device__ __align__(16) ull   g_maskB[TT];
__device__ unsigned g_cnt[2][8];     // per-direction, per-u-chunk h-publication counters

// ---------------- helpers ----------------
__device__ __forceinline__ ull fma2(ull a, ull b, ull c) {
    ull d;
    asm("fma.rn.f32x2 %0, %1, %2, %3;" : "=l"(d) : "l"(a), "l"(b), "l"(c));
    return d;
}
__device__ __forceinline__ ull add2(ull a, ull b) {
    ull d;
    asm("add.rn.f32x2 %0, %1, %2;" : "=l"(d) : "l"(a), "l"(b));
    return d;
}
__device__ __forceinline__ float lo32(ull v) { return __uint_as_float((unsigned)v); }
__device__ __forceinline__ float hi32(ull v) { return __uint_as_float((unsigned)(v >> 32)); }

__device__ __forceinline__ unsigned smem_u32(const void* p) {
    return (unsigned)__cvta_generic_to_shared(p);
}
__device__ __forceinline__ void mb_init(unsigned a, unsigned n) {
    asm volatile("mbarrier.init.shared.b64 [%0], %1;" :: "r"(a), "r"(n) : "memory");
}
__device__ __forceinline__ void mb_expect(unsigned a, unsigned bytes) {
    asm volatile("mbarrier.arrive.expect_tx.shared.b64 _, [%0], %1;" :: "r"(a), "r"(bytes) : "memory");
}
__device__ __forceinline__ void mb_arrive(unsigned a) {
    asm volatile("mbarrier.arrive.shared.b64 _, [%0];" :: "r"(a) : "memory");
}
__device__ __forceinline__ void bulk_g2s(unsigned dst, const void* src, unsigned bytes, unsigned mbar) {
    asm volatile("cp.async.bulk.shared::cluster.global.mbarrier::complete_tx::bytes [%0], [%1], %2, [%3];"
                 :: "r"(dst), "l"(src), "r"(bytes), "r"(mbar) : "memory");
}
__device__ __forceinline__ void mb_wait(unsigned a, unsigned ph) {
    asm volatile(
        "{\n\t"
        ".reg .pred P1;\n"
        "WAIT_LOOP_%=:\n\t"
        "mbarrier.try_wait.parity.acquire.cta.shared::cta.b64 P1, [%0], %1, 0x989680;\n\t"
        "@P1 bra.uni WAIT_DONE_%=;\n\t"
        "bra.uni WAIT_LOOP_%=;\n"
        "WAIT_DONE_%=:\n\t"
        "}" :: "r"(a), "r"(ph) : "memory");
}
__device__ __forceinline__ void named_bar(int id, int nthr) {
    asm volatile("bar.sync %0, %1;" :: "r"(id), "r"(nthr) : "memory");
}

// ---------------- prep: Xt[t][e][b] = emb[enc[b][t]][e] ----------------
__global__ void prep_kernel(const int* __restrict__ enc, const float* __restrict__ emb) {
    int t = blockIdx.x;
    __shared__ int tok[BB];
    if (threadIdx.x < BB) tok[threadIdx.x] = enc[threadIdx.x * TT + t];
    __syncthreads();
    for (int i = threadIdx.x; i < BB * (EE / 4); i += blockDim.x) {
        int e4 = i >> 6;
        int b  = i & 63;
        float4 v = *(const float4*)(emb + (size_t)tok[b] * EE + e4 * 4);
        size_t base = ((size_t)t * EE + (size_t)e4 * 4) * BB + b;
        g_Xt[base]          = v.x;
        g_Xt[base + BB]     = v.y;
        g_Xt[base + 2 * BB] = v.z;
        g_Xt[base + 3 * BB] = v.w;
    }
}

// ---------------- prep_w: duplicate weights into gate-major smem-ready layout ----------
// dst float idx within chunk: k*96 + gate*32 + q*4 + l ; src W[(c*KC+k)*3072 + gate*1024 + p*16 + 2q + (l>>1)]
__global__ void prep_w_kernel(const float* __restrict__ W, int dir, int isX) {
    int c = blockIdx.x;
    int p = blockIdx.y;
    int nch = isX ? NCH_X : NCH_WH;
    float* base = isX ? g_Wxd : g_Whd;
    float* o = base + (((size_t)dir * 64 + p) * nch + c) * WCH;
    for (int i = threadIdx.x; i < WCH; i += blockDim.x) {
        int k = i / 96;   int rem = i - k * 96;
        int gate = rem >> 5;  int r2 = rem & 31;
        int q = r2 >> 2;  int l = r2 & 3;
        o[i] = W[(size_t)(c * KC + k) * 3072 + (gate << 10) + p * 16 + 2 * q + (l >> 1)];
    }
}

// ---------------- mask: pack enc!=0 into one uint64 per t ----------------
__global__ void mask_kernel(const int* __restrict__ enc) {
    int t = blockIdx.x * blockDim.x + threadIdx.x;
    if (t < TT) {
        ull m = 0;
        for (int b = 0; b < BB; b++)
            m |= (ull)(enc[b * TT + t] != 0) << b;
        g_maskB[t] = m;
    }
}

// ---------------- init: h0 -> g_Ht[dir][0]; reset counters ----------------
__global__ void init_kernel(const float* __restrict__ h0f, const float* __restrict__ h0b) {
    int i = blockIdx.x * blockDim.x + threadIdx.x;  // 0 .. 131071
    if (i < 16) g_cnt[i >> 3][i & 7] = 0u;
    int d = i >> 16;
    int r = i & 65535;
    int u = r >> 6;
    int b = r & 63;
    const float* h0 = d ? h0b : h0f;
    g_Ht[d][0][u * BB + b] = h0[b * UU + u];
}

// ---------------- per-chunk compute (identical to v15) ----------------
__device__ __forceinline__ void compute_chunk(const float* as, const float* ws,
                                              int g, int jp, int bq,
                                              ull* az, ull* ar, ull* ah) {
    const char* wb = (const char*)ws + jp * 16 + (size_t)g * 32 * 384;
    const char* ab = (const char*)as + bq * 16 + (size_t)g * 32 * 256;
#pragma unroll 8
    for (int k = 0; k < 32; k++) {
        ulonglong2 wz = *(const ulonglong2*)(wb + (size_t)k * 384);
        ulonglong2 wr = *(const ulonglong2*)(wb + (size_t)k * 384 + 128);
        ulonglong2 wh = *(const ulonglong2*)(wb + (size_t)k * 384 + 256);
        ulonglong2 a  = *(const ulonglong2*)(ab + (size_t)k * 256);
        az[0] = fma2(a.x, wz.x, az[0]);  az[1] = fma2(a.y, wz.x, az[1]);
        az[2] = fma2(a.x, wz.y, az[2]);  az[3] = fma2(a.y, wz.y, az[3]);
        ar[0] = fma2(a.x, wr.x, ar[0]);  ar[1] = fma2(a.y, wr.x, ar[1]);
        ar[2] = fma2(a.x, wr.y, ar[2]);  ar[3] = fma2(a.y, wr.y, ar[3]);
        ah[0] = fma2(a.x, wh.x, ah[0]);  ah[1] = fma2(a.y, wh.x, ah[1]);
        ah[2] = fma2(a.x, wh.y, ah[2]);  ah[3] = fma2(a.y, wh.y, ah[3]);
    }
}

// ---------------- persistent recurrent kernel ----------------
__global__ void __launch_bounds__(NTHR, 1)
gru_kernel(const float* __restrict__ b_f, const float* __restrict__ b_b,
           float* __restrict__ out) {
    extern __shared__ __align__(128) char smem[];
    const unsigned smb = smem_u32(smem);
    ull*  redp  = (ull*)(smem + RED_OFF);
    ull*  maskS = (ull*)(smem + MASK_OFF);
    const unsigned FULL0  = smb + MBAR_OFF;
    const unsigned EMPTY0 = smb + MBAR_OFF + 16;

    const int bid = blockIdx.x, tid = threadIdx.x;
    const int d   = bid >> 6;
    const int p   = bid & 63;

    // one-time init: barriers + mask (all 544 threads participate, then split)
    if (tid == 0) {
        mb_init(FULL0, 1);      mb_init(FULL0 + 8, 1);
        mb_init(EMPTY0, 16);    mb_init(EMPTY0 + 8, 16);
    }
    for (int i = tid; i < TT; i += NTHR) maskS[i] = g_maskB[i];
    __syncthreads();

    const float* whd = g_Whd + ((size_t)(d * 64 + p)) * NCH_WH * WCH;
    const float* wxd = g_Wxd + ((size_t)(d * 64 + p)) * NCH_X  * WCH;

    // ================= producer warp (warp 16) =================
    if (tid >= 512) {
        if (tid == 512) {
            unsigned fc = 0;
#define PFILL(WSRC, ASRC)                                                     \
            do {                                                              \
                unsigned _b = fc & 1;                                         \
                mb_wait(EMPTY0 + _b * 8, (((fc >> 1) & 1) ^ 1));              \
                unsigned _mb = FULL0 + _b * 8;                                \
                mb_expect(_mb, BUF_BYTES);                                    \
                bulk_g2s(smb + _b * BUF_BYTES, (WSRC), BUFW_BYTES, _mb);      \
                bulk_g2s(smb + _b * BUF_BYTES + BUFW_BYTES, (ASRC), BUFA_BYTES, _mb); \
                fc++;                                                         \
            } while (0)

            // prologue: X(t0)
            {
                const int t0 = d ? (TT - 1) : 0;
                const float* xa = g_Xt + (size_t)t0 * EE * BB;
                for (int c = 0; c < NCH_X; c++) PFILL(wxd + c * WCH, xa + (size_t)c * ACH);
            }
            for (int s = 0; s < TT; s++) {
                const float* ha = g_Ht[d][s & 1];
                const unsigned tgt = (unsigned)s * 8;
                for (int c = 0; c < NCH_WH; c++) {
                    if (s > 0) {
                        volatile unsigned* pc = &g_cnt[d][c];
                        while (*pc < tgt) { __nanosleep(32); }
                        __threadfence();
                    }
                    PFILL(whd + (size_t)c * WCH, ha + (size_t)c * ACH);
                }
                if (s < TT - 1) {
                    const int tn = d ? (TT - 2 - s) : (s + 1);
                    const float* xa = g_Xt + (size_t)tn * EE * BB;
                    for (int c = 0; c < NCH_X; c++) PFILL(wxd + c * WCH, xa + (size_t)c * ACH);
                }
            }
#undef PFILL
        }
        return;   // producer warp exits after queueing all fills
    }

    // ================= compute warps (tid < 512) =================
    const int g   = tid >> 7;
    const int r   = tid & 127;
    const int w4  = r >> 5;
    const int ln  = r & 31;
    const int jp  = (w4 & 1) * 4 + (ln >> 3);
    const int bq  = (w4 >> 1) * 8 + (ln & 7);
    const int j0  = p << 4;
    const int jO  = j0 + 2 * jp + (g >> 1);
    const int bO  = 4 * bq + 2 * (g & 1);
    const bool lane0 = (ln == 0) && (g * 0 == 0) && ((tid & 31) == 0);

    const float* bias = d ? b_b : b_f;
    const float bz = bias[jO]        + bias[3072 + jO];
    const float br = bias[1024 + jO] + bias[4096 + jO];
    const float bx = bias[2048 + jO];
    const float bh = bias[5120 + jO];

    float hreg[2], oreg[2];
#pragma unroll
    for (int l = 0; l < 2; l++) {
        hreg[l] = g_Ht[d][0][jO * BB + bO + l];
        oreg[l] = 0.f;
    }

    ull az[4], ar[4], axh[4], ahh[4];
#pragma unroll
    for (int i = 0; i < 4; i++) { az[i] = 0; ar[i] = 0; axh[i] = 0; ahh[i] = 0; }

    unsigned cc = 0;

#define CONSUME(AZ, AR, AH)                                                   \
    do {                                                                      \
        unsigned _b = cc & 1;                                                 \
        mb_wait(FULL0 + _b * 8, (cc >> 1) & 1);                               \
        const float* _ws = (const float*)(smem + _b * BUF_BYTES);             \
        const float* _as = (const float*)(smem + _b * BUF_BYTES + BUFW_BYTES);\
        compute_chunk(_as, _ws, g, jp, bq, (AZ), (AR), (AH));                 \
        __syncwarp();                                                         \
        if (lane0) mb_arrive(EMPTY0 + _b * 8);                                \
        cc++;                                                                 \
    } while (0)

    // prologue: X phase of step 0
    for (int c = 0; c < NCH_X; c++) CONSUME(az, ar, axh);

    for (int s = 0;; s++) {
        const int t   = d ? (TT - 1 - s) : s;
        const int par = s & 1;

        // Wh phase
        for (int c = 0; c < NCH_WH; c++) CONSUME(az, ar, ahh);

        // cross-group reduce
#pragma unroll
        for (int q = 0; q < 4; q++) {
            if (q == g) continue;
            int c2 = g - (g > q ? 1 : 0);
            ull* dst = redp + (size_t)(((q << 7) + r) * 3 + c2) * 4;
            dst[0] = az[q]; dst[1] = ar[q]; dst[2] = axh[q]; dst[3] = ahh[q];
        }
        named_bar(1, 512);

        ull sz = az[g], sr = ar[g], sx = axh[g], sh = ahh[g];
        {
            const ull* src = redp + (size_t)(((g << 7) + r) * 3) * 4;
#pragma unroll
            for (int c2 = 0; c2 < 3; c2++) {
                const ull* sp = src + c2 * 4;
                sz = add2(sz, sp[0]); sr = add2(sr, sp[1]);
                sx = add2(sx, sp[2]); sh = add2(sh, sp[3]);
            }
        }

        // epilogue
        {
            const ull mv = maskS[t];
            const size_t ocol = (size_t)t * 2048 + (size_t)d * UU + jO;
            float hv[2];
#pragma unroll
            for (int l = 0; l < 2; l++) {
                const bool m = (mv >> (bO + l)) & 1ull;
                float zs = l ? hi32(sz) : lo32(sz);
                float rs = l ? hi32(sr) : lo32(sr);
                float xs = l ? hi32(sx) : lo32(sx);
                float hs = l ? hi32(sh) : lo32(sh);
                float ez = __expf(-(zs + bz));
                float z  = __fdividef(1.f, 1.f + ez);
                float er = __expf(-(rs + br));
                float rg = __fdividef(1.f, 1.f + er);
                float hc = tanhf(xs + bx + rg * (hs + bh));
                float hn = z * hreg[l] + (1.f - z) * hc;
                hn = m ? hn : hreg[l];
                float o = m ? hn : oreg[l];
                hreg[l] = hn;
                oreg[l] = o;
                hv[l] = hn;
            }
            float* hdst = g_Ht[d][par ^ 1];
            *(float2*)&hdst[jO * BB + bO] = make_float2(hv[0], hv[1]);
            out[(size_t)bO * (TT * 2048) + ocol]       = oreg[0];
            out[(size_t)(bO + 1) * (TT * 2048) + ocol] = oreg[1];
        }

        if (s == TT - 1) break;

        // publish h(s+1): block-wide completion, then one arrive on this block's u-chunk counter
        named_bar(1, 512);
        if (tid == 0) { __threadfence(); atomicAdd(&g_cnt[d][p >> 3], 1u); }

        // zero accs; X phase of step s+1 (producer keeps the ring fed; no global wait here)
#pragma unroll
        for (int i = 0; i < 4; i++) { az[i] = 0; ar[i] = 0; axh[i] = 0; ahh[i] = 0; }
        for (int c = 0; c < NCH_X; c++) CONSUME(az, ar, axh);
    }

    // final state
    {
        const size_t STATE_OFF = (size_t)BB * TT * 2048;
#pragma unroll
        for (int l = 0; l < 2; l++)
            out[STATE_OFF + (size_t)(bO + l) * 2048 + (size_t)d * UU + jO] = hreg[l];
    }
#undef CONSUME
}

// ---------------- launcher ----------------
extern "C" void kernel_launch(void* const* d_in, const int* in_sizes, int n_in,
                              void* d_out, int out_size) {
    (void)in_sizes; (void)n_in; (void)out_size;
    const int*   enc = (const int*)  d_in[0];
    const float* h0f = (const float*)d_in[1];
    const float* h0b = (const float*)d_in[2];
    const float* emb = (const float*)d_in[3];
    const float* Wxf = (const float*)d_in[4];
    const float* Whf = (const float*)d_in[5];
    const float* bf  = (const float*)d_in[6];
    const float* Wxb = (const float*)d_in[7];
    const float* Whb = (const float*)d_in[8];
    const float* bb  = (const float*)d_in[9];
    float* out = (float*)d_out;

    cudaFuncSetAttribute(gru_kernel, cudaFuncAttributeMaxDynamicSharedMemorySize, SMEM_TOTAL);

    prep_kernel<<<TT, 256>>>(enc, emb);
    prep_w_kernel<<<dim3(NCH_WH, 64), 256>>>(Whf, 0, 0);
    prep_w_kernel<<<dim3(NCH_WH, 64), 256>>>(Whb, 1, 0);
    prep_w_kernel<<<dim3(NCH_X, 64), 256>>>(Wxf, 0, 1);
    prep_w_kernel<<<dim3(NCH_X, 64), 256>>>(Wxb, 1, 1);
    mask_kernel<<<2, 256>>>(enc);
    init_kernel<<<512, 256>>>(h0f, h0b);
    gru_kernel<<<NB, NTHR, SMEM_TOTAL>>>(bf, bb, out);
}